// round 1
// baseline (speedup 1.0000x reference)
#include <cuda_runtime.h>
#include <cstdint>

#define BB   32
#define NN   25200
#define NCH  85
#define NCL  80
#define KNMS 4096
#define CONF_T 0.25f
#define IOU_T  0.45f
#define MAXDET 1000
#define MAXWH  7680.0f
#define NROWS (BB * NN)

// ---------------- scratch (static device globals; no allocation) ----------------
__device__ float              g_conf[NROWS];
__device__ unsigned char      g_j[NROWS];
__device__ unsigned char      g_flags[NROWS];      // bit0: xc, bit1: w
__device__ int                g_A[NROWS];          // per image: xc-true indices ascending
__device__ unsigned long long g_key[BB * KNMS];    // (conf_bits<<32) | ~rank
__device__ float              g_bx[BB * KNMS * 4]; // boxes (class-offset xyxy), indexed by rank
__device__ int                g_cntA[BB];
__device__ int                g_cntW[BB];
__device__ int                g_sm[BB * KNMS];     // sorted: pre-sort rank payload
__device__ float              g_sx1[BB * KNMS];
__device__ float              g_sy1[BB * KNMS];
__device__ float              g_sx2[BB * KNMS];
__device__ float              g_sy2[BB * KNMS];

// ---------------- K1a: per-row conf / argmax / flags (warp per row) ----------------
__global__ void k_score(const float* __restrict__ p) {
    int row = blockIdx.x * (blockDim.x >> 5) + (threadIdx.x >> 5);
    if (row >= NROWS) return;
    int lane = threadIdx.x & 31;
    const float* pr = p + (size_t)row * NCH;

    float v0 = pr[lane];
    float v1 = pr[lane + 32];
    float v2 = (lane < 21) ? pr[lane + 64] : 0.0f;
    float obj = __shfl_sync(0xffffffffu, v0, 4);

    float bv = -3.4e38f; int bi = 1 << 20;
    if (lane >= 5) { bv = obj * v0; bi = lane - 5; }           // cols 5..31  -> cls 0..26
    { float s = obj * v1; int i1 = lane + 27;                  // cols 37..68 -> cls 32..63? no:
      // col = lane+32 in [32,63] -> cls idx = lane+27 in [27,58]
      if (s > bv) { bv = s; bi = i1; } }
    if (lane < 21) { float s = obj * v2; int i2 = lane + 59;   // cols 64..84 -> cls 59..79
      if (s > bv) { bv = s; bi = i2; } }

    // reduce: max value, ties -> smallest class index (matches jnp first-argmax)
    for (int off = 16; off; off >>= 1) {
        float ov = __shfl_xor_sync(0xffffffffu, bv, off);
        int   oi = __shfl_xor_sync(0xffffffffu, bi, off);
        if (ov > bv || (ov == bv && oi < bi)) { bv = ov; bi = oi; }
    }
    if (lane == 0) {
        g_conf[row] = bv;
        g_j[row] = (unsigned char)bi;
        bool xc = obj > CONF_T;
        bool w  = xc && (bv > CONF_T);
        g_flags[row] = (unsigned char)((xc ? 1 : 0) | (w ? 2 : 0));
    }
}

// ---------------- K1b: stable compaction per image ----------------
__global__ void k_compact(const float* __restrict__ p) {
    int b = blockIdx.x;
    int tid = threadIdx.x, lane = tid & 31, wid = tid >> 5;
    __shared__ int sA[32], sW[32];
    __shared__ int baseA, baseW;
    if (tid == 0) { baseA = 0; baseW = 0; }
    __syncthreads();

    for (int base = 0; base < NN; base += 1024) {
        int i = base + tid;
        unsigned f = (i < NN) ? g_flags[b * NN + i] : 0u;
        unsigned mA = __ballot_sync(0xffffffffu, f & 1u);
        unsigned mW = __ballot_sync(0xffffffffu, (f >> 1) & 1u);
        if (lane == 0) { sA[wid] = __popc(mA); sW[wid] = __popc(mW); }
        __syncthreads();
        int preA = 0, preW = 0;
        for (int w2 = 0; w2 < wid; w2++) { preA += sA[w2]; preW += sW[w2]; }
        unsigned lmask = (1u << lane) - 1u;
        if (f & 1u) {
            int pos = baseA + preA + __popc(mA & lmask);
            g_A[b * NN + pos] = i;
        }
        if (f & 2u) {
            int pos = baseW + preW + __popc(mW & lmask);
            if (pos < KNMS) {
                float conf = g_conf[b * NN + i];
                unsigned cb = __float_as_uint(conf);
                g_key[b * KNMS + pos] =
                    ((unsigned long long)cb << 32) | (unsigned long long)(~(unsigned)pos);
                const float* pr = p + ((size_t)b * NN + i) * NCH;
                float x = pr[0], y = pr[1], ww = pr[2], hh = pr[3];
                float off = (float)g_j[b * NN + i] * MAXWH;
                float hw = __fmul_rn(ww, 0.5f);
                float hv = __fmul_rn(hh, 0.5f);
                float* bx = g_bx + ((size_t)b * KNMS + pos) * 4;
                bx[0] = __fadd_rn(__fsub_rn(x, hw), off);
                bx[1] = __fadd_rn(__fsub_rn(y, hv), off);
                bx[2] = __fadd_rn(__fadd_rn(x, hw), off);
                bx[3] = __fadd_rn(__fadd_rn(y, hv), off);
            }
        }
        __syncthreads();
        if (tid == 0) {
            int tA = 0, tW = 0;
            for (int w2 = 0; w2 < 32; w2++) { tA += sA[w2]; tW += sW[w2]; }
            baseA += tA; baseW += tW;
        }
        __syncthreads();
    }
    if (tid == 0) { g_cntA[b] = baseA; g_cntW[b] = baseW; }
}

// ---------------- K2: stable descending sort by conf (bitonic, 4096) ----------------
__global__ void k_sort() {
    int b = blockIdx.x;
    int tid = threadIdx.x;
    __shared__ unsigned long long sk[KNMS];
    int cnt = g_cntW[b]; if (cnt > KNMS) cnt = KNMS;
    for (int t = tid; t < KNMS; t += 1024)
        sk[t] = (t < cnt) ? g_key[b * KNMS + t] : 0ull;
    __syncthreads();
    for (int k = 2; k <= KNMS; k <<= 1) {
        for (int j = k >> 1; j > 0; j >>= 1) {
            for (int t = tid; t < KNMS; t += 1024) {
                int l = t ^ j;
                if (l > t) {
                    unsigned long long a = sk[t], c = sk[l];
                    bool up = (t & k) == 0;               // descending network
                    bool sw = up ? (a < c) : (a > c);
                    if (sw) { sk[t] = c; sk[l] = a; }
                }
            }
            __syncthreads();
        }
    }
    for (int t = tid; t < KNMS; t += 1024) {
        if (t < cnt) {
            unsigned long long key = sk[t];
            unsigned m = ~(unsigned)key;
            g_sm[b * KNMS + t] = (int)m;
            const float* bx = g_bx + ((size_t)b * KNMS + m) * 4;
            g_sx1[b * KNMS + t] = bx[0];
            g_sy1[b * KNMS + t] = bx[1];
            g_sx2[b * KNMS + t] = bx[2];
            g_sy2[b * KNMS + t] = bx[3];
        }
    }
}

// ---------------- K3: greedy NMS + cap 1000 + output accumulation ----------------
__global__ void k_nms(const float* __restrict__ p, float* __restrict__ out) {
    int b = blockIdx.x;
    int tid = threadIdx.x;
    extern __shared__ float sdyn[];
    float* sx1 = sdyn;
    float* sy1 = sdyn + KNMS;
    float* sx2 = sdyn + 2 * KNMS;
    float* sy2 = sdyn + 3 * KNMS;
    float* sar = sdyn + 4 * KNMS;
    int*   sm  = (int*)(sdyn + 5 * KNMS);
    __shared__ unsigned long long rem[KNMS / 64];
    __shared__ int s_cnt;
    __shared__ int s_picks[MAXDET];
    __shared__ float s_out[NCL];

    int C = g_cntW[b]; if (C > KNMS) C = KNMS;
    for (int t = tid; t < C; t += 1024) {
        float x1 = g_sx1[b * KNMS + t];
        float y1 = g_sy1[b * KNMS + t];
        float x2 = g_sx2[b * KNMS + t];
        float y2 = g_sy2[b * KNMS + t];
        sx1[t] = x1; sy1[t] = y1; sx2[t] = x2; sy2[t] = y2;
        sar[t] = __fmul_rn(__fsub_rn(x2, x1), __fsub_rn(y2, y1));
        sm[t]  = g_sm[b * KNMS + t];
    }
    if (tid < KNMS / 64) rem[tid] = 0ull;
    if (tid == 0) s_cnt = 0;
    if (tid < NCL) s_out[tid] = 0.0f;
    __syncthreads();

    for (int i = 0; i < C; i++) {
        if (s_cnt >= MAXDET) break;   // coherent: read after the barrier at loop tail
        bool doi = ((rem[i >> 6] >> (i & 63)) & 1ull) == 0ull;
        if (doi) {
            if (tid == 0) { s_picks[s_cnt] = sm[i]; s_cnt = s_cnt + 1; }
            float bx1 = sx1[i], by1 = sy1[i], bx2 = sx2[i], by2 = sy2[i], ba = sar[i];
            for (int j = i + 1 + tid; j < C; j += 1024) {
                float iw = __fsub_rn(fminf(sx2[j], bx2), fmaxf(sx1[j], bx1));
                float ih = __fsub_rn(fminf(sy2[j], by2), fmaxf(sy1[j], by1));
                float inter = __fmul_rn(fmaxf(iw, 0.0f), fmaxf(ih, 0.0f));
                float denom = __fsub_rn(__fadd_rn(sar[j], ba), inter);
                float iou = __fdiv_rn(inter, denom);
                if (iou > IOU_T)
                    atomicOr(&rem[j >> 6], 1ull << (j & 63));
            }
        }
        __syncthreads();
    }
    __syncthreads();

    int cnt = s_cnt; if (cnt > MAXDET) cnt = MAXDET;
    int c = tid & 127, grp = tid >> 7;   // 8 accumulation groups
    if (c < NCL) {
        float acc = 0.0f;
        for (int t = grp; t < cnt; t += 8) {
            int m = s_picks[t];
            int rowi = g_A[b * NN + m];            // the reference's idx1[order] "pick"
            const float* pr = p + ((size_t)b * NN + rowi) * NCH;
            acc += pr[4] * pr[5 + c];
        }
        atomicAdd(&s_out[c], acc);
    }
    __syncthreads();
    if (tid < NCL) out[b * NCL + tid] = s_out[tid];
}

// ---------------- launcher ----------------
extern "C" void kernel_launch(void* const* d_in, const int* in_sizes, int n_in,
                              void* d_out, int out_size) {
    const float* p = (const float*)d_in[0];
    float* out = (float*)d_out;

    int warps_per_block = 8;
    int nblocks = (NROWS + warps_per_block - 1) / warps_per_block;
    k_score<<<nblocks, 256>>>(p);
    k_compact<<<BB, 1024>>>(p);
    k_sort<<<BB, 1024>>>();
    cudaFuncSetAttribute(k_nms, cudaFuncAttributeMaxDynamicSharedMemorySize,
                         (5 * KNMS + KNMS) * 4);
    k_nms<<<BB, 1024, (5 * KNMS + KNMS) * 4>>>(p, out);
}

// round 2
// speedup vs baseline: 3.6921x; 3.6921x over previous
#include <cuda_runtime.h>
#include <cstdint>

#define BB   32
#define NN   25200
#define NCH  85
#define NCL  80
#define KNMS 4096
#define CONF_T 0.25f
#define IOU_T  0.45f
#define MAXDET 1000
#define MAXWH  7680.0f
#define NROWS (BB * NN)
#define CLCAP 256

// ---------------- scratch (static device globals; no allocation) ----------------
__device__ float              g_conf[NROWS];
__device__ unsigned char      g_j[NROWS];
__device__ unsigned char      g_flags[NROWS];      // bit0: xc, bit1: w
__device__ int                g_A[NROWS];          // per image: xc-true indices ascending
__device__ unsigned long long g_key[BB * KNMS];    // (conf_bits<<32) | ~rank
__device__ float              g_bx[BB * KNMS * 4]; // boxes (class-offset xyxy), indexed by rank
__device__ int                g_cntA[BB];
__device__ int                g_cntW[BB];
__device__ int                g_sm[BB * KNMS];     // sorted: pre-sort rank payload
__device__ float              g_sx1[BB * KNMS];
__device__ float              g_sy1[BB * KNMS];
__device__ float              g_sx2[BB * KNMS];
__device__ float              g_sy2[BB * KNMS];

// ---------------- K1a: per-row conf / argmax / flags (warp per row) ----------------
__global__ void k_score(const float* __restrict__ p) {
    int row = blockIdx.x * (blockDim.x >> 5) + (threadIdx.x >> 5);
    if (row >= NROWS) return;
    int lane = threadIdx.x & 31;
    const float* pr = p + (size_t)row * NCH;

    float v0 = pr[lane];
    float v1 = pr[lane + 32];
    float v2 = (lane < 21) ? pr[lane + 64] : 0.0f;
    float obj = __shfl_sync(0xffffffffu, v0, 4);

    float bv = -3.4e38f; int bi = 1 << 20;
    if (lane >= 5) { bv = obj * v0; bi = lane - 5; }           // cols 5..31  -> cls 0..26
    { float s = obj * v1; int i1 = lane + 27;                  // cols 32..63 -> cls 27..58
      if (s > bv) { bv = s; bi = i1; } }
    if (lane < 21) { float s = obj * v2; int i2 = lane + 59;   // cols 64..84 -> cls 59..79
      if (s > bv) { bv = s; bi = i2; } }

    for (int off = 16; off; off >>= 1) {
        float ov = __shfl_xor_sync(0xffffffffu, bv, off);
        int   oi = __shfl_xor_sync(0xffffffffu, bi, off);
        if (ov > bv || (ov == bv && oi < bi)) { bv = ov; bi = oi; }
    }
    if (lane == 0) {
        g_conf[row] = bv;
        g_j[row] = (unsigned char)bi;
        bool xc = obj > CONF_T;
        bool w  = xc && (bv > CONF_T);
        g_flags[row] = (unsigned char)((xc ? 1 : 0) | (w ? 2 : 0));
    }
}

// ---------------- K1b: stable compaction per image ----------------
__global__ void k_compact(const float* __restrict__ p) {
    int b = blockIdx.x;
    int tid = threadIdx.x, lane = tid & 31, wid = tid >> 5;
    __shared__ int sA[32], sW[32];
    __shared__ int baseA, baseW;
    if (tid == 0) { baseA = 0; baseW = 0; }
    __syncthreads();

    for (int base = 0; base < NN; base += 1024) {
        int i = base + tid;
        unsigned f = (i < NN) ? g_flags[b * NN + i] : 0u;
        unsigned mA = __ballot_sync(0xffffffffu, f & 1u);
        unsigned mW = __ballot_sync(0xffffffffu, (f >> 1) & 1u);
        if (lane == 0) { sA[wid] = __popc(mA); sW[wid] = __popc(mW); }
        __syncthreads();
        int preA = 0, preW = 0;
        for (int w2 = 0; w2 < wid; w2++) { preA += sA[w2]; preW += sW[w2]; }
        unsigned lmask = (1u << lane) - 1u;
        if (f & 1u) {
            int pos = baseA + preA + __popc(mA & lmask);
            g_A[b * NN + pos] = i;
        }
        if (f & 2u) {
            int pos = baseW + preW + __popc(mW & lmask);
            if (pos < KNMS) {
                float conf = g_conf[b * NN + i];
                unsigned cb = __float_as_uint(conf);
                g_key[b * KNMS + pos] =
                    ((unsigned long long)cb << 32) | (unsigned long long)(~(unsigned)pos);
                const float* pr = p + ((size_t)b * NN + i) * NCH;
                float x = pr[0], y = pr[1], ww = pr[2], hh = pr[3];
                float off = (float)g_j[b * NN + i] * MAXWH;
                float hw = __fmul_rn(ww, 0.5f);
                float hv = __fmul_rn(hh, 0.5f);
                float* bx = g_bx + ((size_t)b * KNMS + pos) * 4;
                bx[0] = __fadd_rn(__fsub_rn(x, hw), off);
                bx[1] = __fadd_rn(__fsub_rn(y, hv), off);
                bx[2] = __fadd_rn(__fadd_rn(x, hw), off);
                bx[3] = __fadd_rn(__fadd_rn(y, hv), off);
            }
        }
        __syncthreads();
        if (tid == 0) {
            int tA = 0, tW = 0;
            for (int w2 = 0; w2 < 32; w2++) { tA += sA[w2]; tW += sW[w2]; }
            baseA += tA; baseW += tW;
        }
        __syncthreads();
    }
    if (tid == 0) { g_cntA[b] = baseA; g_cntW[b] = baseW; }
}

// ---------------- K2: stable descending sort by conf (bitonic, 4096) ----------------
__global__ void k_sort() {
    int b = blockIdx.x;
    int tid = threadIdx.x;
    __shared__ unsigned long long sk[KNMS];
    int cnt = g_cntW[b]; if (cnt > KNMS) cnt = KNMS;
    for (int t = tid; t < KNMS; t += 1024)
        sk[t] = (t < cnt) ? g_key[b * KNMS + t] : 0ull;
    __syncthreads();
    for (int k = 2; k <= KNMS; k <<= 1) {
        for (int j = k >> 1; j > 0; j >>= 1) {
            for (int t = tid; t < KNMS; t += 1024) {
                int l = t ^ j;
                if (l > t) {
                    unsigned long long a = sk[t], c = sk[l];
                    bool up = (t & k) == 0;
                    bool sw = up ? (a < c) : (a > c);
                    if (sw) { sk[t] = c; sk[l] = a; }
                }
            }
            __syncthreads();
        }
    }
    for (int t = tid; t < KNMS; t += 1024) {
        if (t < cnt) {
            unsigned long long key = sk[t];
            unsigned m = ~(unsigned)key;
            g_sm[b * KNMS + t] = (int)m;
            const float* bx = g_bx + ((size_t)b * KNMS + m) * 4;
            g_sx1[b * KNMS + t] = bx[0];
            g_sy1[b * KNMS + t] = bx[1];
            g_sx2[b * KNMS + t] = bx[2];
            g_sy2[b * KNMS + t] = bx[3];
        }
    }
}

// ---------------- K3: per-class greedy NMS + cap 1000 + output ----------------
// Classes never overlap (offset 7680 >> max box extent ~724), so cross-class
// IoU is exactly 0.0f and the global greedy decomposes into 80 independent
// per-class greedy chains. One warp per class, no block barriers in the greedy.
__global__ void k_nms(const float* __restrict__ p, float* __restrict__ out) {
    int b = blockIdx.x;
    int tid = threadIdx.x, lane = tid & 31, wid = tid >> 5;
    const unsigned FULL = 0xffffffffu;

    extern __shared__ int idyn[];
    float* sx1 = (float*)idyn;              // 4096
    float* sy1 = sx1 + KNMS;                // 4096
    float* sx2 = sy1 + KNMS;                // 4096
    float* sy2 = sx2 + KNMS;                // 4096
    float* sar = sy2 + KNMS;                // 4096
    int*   picks = idyn + 5 * KNMS;         // 1024 (MAXDET rounded)
    unsigned short* lists = (unsigned short*)(idyn + 5 * KNMS + 1024); // 32*256 u16 = 4096 ints
    unsigned char* scl   = (unsigned char*)(idyn + 5 * KNMS + 1024 + 4096);  // 4096 B
    unsigned char* keepf = (unsigned char*)(idyn + 5 * KNMS + 1024 + 4096 + 1024); // 4096 B
    __shared__ int wsum[32];
    __shared__ int s_total;
    __shared__ float s_out[NCL];

    int C = g_cntW[b]; if (C > KNMS) C = KNMS;

    for (int t = tid; t < KNMS; t += 1024) {
        keepf[t] = 0;
        if (t < C) {
            float x1 = g_sx1[b * KNMS + t];
            float y1 = g_sy1[b * KNMS + t];
            float x2 = g_sx2[b * KNMS + t];
            float y2 = g_sy2[b * KNMS + t];
            sx1[t] = x1; sy1[t] = y1; sx2[t] = x2; sy2[t] = y2;
            sar[t] = __fmul_rn(__fsub_rn(x2, x1), __fsub_rn(y2, y1));
            scl[t] = (unsigned char)__float2int_rn(x1 * (1.0f / MAXWH));
        } else {
            scl[t] = 255;
        }
    }
    if (tid < NCL) s_out[tid] = 0.0f;
    __syncthreads();

    // per-class greedy: warp wid handles classes wid, wid+32, wid+64
    for (int c = wid; c < NCL; c += 32) {
        unsigned short* lst = lists + wid * CLCAP;
        int n = 0;
        for (int base = 0; base < C; base += 32) {
            int t = base + lane;
            bool m = (t < C) && (scl[t] == (unsigned char)c);
            unsigned bal = __ballot_sync(FULL, m);
            if (m) {
                int pos = n + __popc(bal & ((1u << lane) - 1u));
                if (pos < CLCAP) lst[pos] = (unsigned short)t;
            }
            n += __popc(bal);
        }
        if (n > CLCAP) n = CLCAP;

        unsigned rm = 0;  // removed bits: entry e owned by lane e&31, bit e>>5
        for (int i = 0; i < n; i++) {
            unsigned rmi = __shfl_sync(FULL, rm, i & 31);
            if ((rmi >> (i >> 5)) & 1u) continue;   // uniform
            int ti = lst[i];
            if (lane == 0) keepf[ti] = 1;
            float bx1 = sx1[ti], by1 = sy1[ti], bx2 = sx2[ti], by2 = sy2[ti];
            float ba = sar[ti];
            for (int k = 0, e = lane; e < n; k++, e += 32) {
                if (e > i && !((rm >> k) & 1u)) {
                    int tj = lst[e];
                    float iw = __fsub_rn(fminf(sx2[tj], bx2), fmaxf(sx1[tj], bx1));
                    float ih = __fsub_rn(fminf(sy2[tj], by2), fmaxf(sy1[tj], by1));
                    float inter = __fmul_rn(fmaxf(iw, 0.0f), fmaxf(ih, 0.0f));
                    float denom = __fsub_rn(__fadd_rn(sar[tj], ba), inter);
                    if (__fdiv_rn(inter, denom) > IOU_T) rm |= (1u << k);
                }
            }
            __syncwarp();
        }
    }
    __syncthreads();

    // block prefix-scan over keep flags (4 elements per thread), cap at MAXDET
    int t0 = tid * 4;
    int k0 = keepf[t0], k1 = keepf[t0 + 1], k2 = keepf[t0 + 2], k3 = keepf[t0 + 3];
    int sum4 = k0 + k1 + k2 + k3;
    int s = sum4;
    for (int o = 1; o < 32; o <<= 1) {
        int v = __shfl_up_sync(FULL, s, o);
        if (lane >= o) s += v;
    }
    if (lane == 31) wsum[wid] = s;
    __syncthreads();
    if (wid == 0) {
        int w = wsum[lane];
        for (int o = 1; o < 32; o <<= 1) {
            int v = __shfl_up_sync(FULL, w, o);
            if (lane >= o) w += v;
        }
        wsum[lane] = w;
        if (lane == 31) s_total = w;
    }
    __syncthreads();
    int base = (wid ? wsum[wid - 1] : 0) + (s - sum4);
    int p0 = base + k0;
    int p1 = p0 + k1;
    int p2 = p1 + k2;
    int p3 = p2 + k3;
    if (k0 && p0 <= MAXDET) picks[p0 - 1] = g_sm[b * KNMS + t0];
    if (k1 && p1 <= MAXDET) picks[p1 - 1] = g_sm[b * KNMS + t0 + 1];
    if (k2 && p2 <= MAXDET) picks[p2 - 1] = g_sm[b * KNMS + t0 + 2];
    if (k3 && p3 <= MAXDET) picks[p3 - 1] = g_sm[b * KNMS + t0 + 3];
    __syncthreads();

    int cnt = s_total; if (cnt > MAXDET) cnt = MAXDET;
    int c = tid & 127, grp = tid >> 7;   // 8 accumulation groups
    if (c < NCL) {
        float acc = 0.0f;
        for (int t = grp; t < cnt; t += 8) {
            int m = picks[t];
            int rowi = g_A[b * NN + m];            // reference's idx1[order] "pick"
            const float* pr = p + ((size_t)b * NN + rowi) * NCH;
            acc += pr[4] * pr[5 + c];
        }
        atomicAdd(&s_out[c], acc);
    }
    __syncthreads();
    if (tid < NCL) out[b * NCL + tid] = s_out[tid];
}

// ---------------- launcher ----------------
extern "C" void kernel_launch(void* const* d_in, const int* in_sizes, int n_in,
                              void* d_out, int out_size) {
    const float* p = (const float*)d_in[0];
    float* out = (float*)d_out;

    int warps_per_block = 8;
    int nblocks = (NROWS + warps_per_block - 1) / warps_per_block;
    k_score<<<nblocks, 256>>>(p);
    k_compact<<<BB, 1024>>>(p);
    k_sort<<<BB, 1024>>>();
    int smem = (5 * KNMS + 1024 + 4096 + 1024 + 1024) * 4;
    cudaFuncSetAttribute(k_nms, cudaFuncAttributeMaxDynamicSharedMemorySize, smem);
    k_nms<<<BB, 1024, smem>>>(p, out);
}

// round 3
// speedup vs baseline: 6.9792x; 1.8903x over previous
#include <cuda_runtime.h>
#include <cstdint>

#define BB   32
#define NN   25200
#define NCH  85
#define NCL  80
#define KNMS 4096
#define CONF_T 0.25f
#define IOU_T  0.45f
#define MAXDET 1000
#define MAXWH  7680.0f
#define NROWS (BB * NN)
#define CLCAP 256
#define FULLM 0xffffffffu

// ---------------- scratch (static device globals; no allocation) ----------------
__device__ int                g_A[NROWS];          // per image: xc-true row indices ascending
__device__ int                g_cntA[BB];
__device__ float              g_cconf[NROWS];      // per xc-candidate conf
__device__ unsigned char      g_cw[NROWS];         // per xc-candidate w flag
__device__ float4             g_cbox[NROWS];       // per xc-candidate class-offset xyxy
__device__ unsigned long long g_key[BB * KNMS];    // (conf_bits<<32) | ~rank
__device__ float4             g_bx[BB * KNMS];     // boxes indexed by w-rank
__device__ int                g_cntW[BB];
__device__ int                g_sm[BB * KNMS];     // sorted: pre-sort w-rank payload
__device__ float              g_sx1[BB * KNMS];
__device__ float              g_sy1[BB * KNMS];
__device__ float              g_sx2[BB * KNMS];
__device__ float              g_sy2[BB * KNMS];

// ---------------- K1: obj-only read + stable xc compaction (1 block/image) ----------------
__global__ void k_compactA(const float* __restrict__ p) {
    int b = blockIdx.x;
    int tid = threadIdx.x, lane = tid & 31, wid = tid >> 5;
    __shared__ int sA[32];
    __shared__ int baseA;
    if (tid == 0) baseA = 0;
    __syncthreads();

    for (int base = 0; base < NN; base += 1024) {
        int i = base + tid;
        bool xc = false;
        if (i < NN) {
            float obj = p[((size_t)b * NN + i) * NCH + 4];
            xc = obj > CONF_T;
        }
        unsigned mA = __ballot_sync(FULLM, xc);
        if (lane == 0) sA[wid] = __popc(mA);
        __syncthreads();
        int pre = 0;
        for (int w2 = 0; w2 < wid; w2++) pre += sA[w2];
        if (xc) {
            int pos = baseA + pre + __popc(mA & ((1u << lane) - 1u));
            g_A[b * NN + pos] = i;
        }
        __syncthreads();
        if (tid == 0) {
            int tot = 0;
            for (int w2 = 0; w2 < 32; w2++) tot += sA[w2];
            baseA += tot;
        }
        __syncthreads();
    }
    if (tid == 0) g_cntA[b] = baseA;
}

// ---------------- K2: per-candidate conf/argmax/box (warp per candidate) ----------------
__global__ void k_cand(const float* __restrict__ p) {
    int b = blockIdx.y;
    int nw = blockDim.x >> 5;
    int widG = blockIdx.x * nw + (threadIdx.x >> 5);
    int lane = threadIdx.x & 31;
    int cnt = g_cntA[b];
    int stride = gridDim.x * nw;

    for (int i = widG; i < cnt; i += stride) {
        int row = g_A[b * NN + i];
        const float* pr = p + ((size_t)b * NN + row) * NCH;
        float v0 = pr[lane];
        float v1 = pr[lane + 32];
        float v2 = (lane < 21) ? pr[lane + 64] : 0.0f;
        float obj = __shfl_sync(FULLM, v0, 4);

        float bv = -3.4e38f; int bi = 1 << 20;
        if (lane >= 5) { bv = obj * v0; bi = lane - 5; }        // cols 5..31  -> cls 0..26
        { float s = obj * v1; int i1 = lane + 27;               // cols 32..63 -> cls 27..58
          if (s > bv) { bv = s; bi = i1; } }
        if (lane < 21) { float s = obj * v2; int i2 = lane + 59;// cols 64..84 -> cls 59..79
          if (s > bv) { bv = s; bi = i2; } }
        for (int off = 16; off; off >>= 1) {
            float ov = __shfl_xor_sync(FULLM, bv, off);
            int   oi = __shfl_xor_sync(FULLM, bi, off);
            if (ov > bv || (ov == bv && oi < bi)) { bv = ov; bi = oi; }
        }
        float x  = __shfl_sync(FULLM, v0, 0);
        float y  = __shfl_sync(FULLM, v0, 1);
        float ww = __shfl_sync(FULLM, v0, 2);
        float hh = __shfl_sync(FULLM, v0, 3);
        if (lane == 0) {
            bool w = bv > CONF_T;
            g_cw[b * NN + i] = w ? 1 : 0;
            if (w) {
                g_cconf[b * NN + i] = bv;
                float off = (float)bi * MAXWH;
                float hw = __fmul_rn(ww, 0.5f);
                float hv = __fmul_rn(hh, 0.5f);
                float4 bx;
                bx.x = __fadd_rn(__fsub_rn(x, hw), off);
                bx.y = __fadd_rn(__fsub_rn(y, hv), off);
                bx.z = __fadd_rn(__fadd_rn(x, hw), off);
                bx.w = __fadd_rn(__fadd_rn(y, hv), off);
                g_cbox[b * NN + i] = bx;
            }
        }
    }
}

// ---------------- K3: stable w compaction -> keys + boxes by rank ----------------
__global__ void k_compactW() {
    int b = blockIdx.x;
    int tid = threadIdx.x, lane = tid & 31, wid = tid >> 5;
    __shared__ int sW[32];
    __shared__ int baseW;
    int cntA = g_cntA[b];
    if (tid == 0) baseW = 0;
    __syncthreads();

    for (int base = 0; base < cntA; base += 1024) {
        int i = base + tid;
        bool w = (i < cntA) && (g_cw[b * NN + i] != 0);
        unsigned mW = __ballot_sync(FULLM, w);
        if (lane == 0) sW[wid] = __popc(mW);
        __syncthreads();
        int pre = 0;
        for (int w2 = 0; w2 < wid; w2++) pre += sW[w2];
        if (w) {
            int pos = baseW + pre + __popc(mW & ((1u << lane) - 1u));
            if (pos < KNMS) {
                unsigned cb = __float_as_uint(g_cconf[b * NN + i]);
                g_key[b * KNMS + pos] =
                    ((unsigned long long)cb << 32) | (unsigned long long)(~(unsigned)pos);
                g_bx[b * KNMS + pos] = g_cbox[b * NN + i];
            }
        }
        __syncthreads();
        if (tid == 0) {
            int tot = 0;
            for (int w2 = 0; w2 < 32; w2++) tot += sW[w2];
            baseW += tot;
        }
        __syncthreads();
    }
    if (tid == 0) g_cntW[b] = baseW;
}

// ---------------- K4: stable descending bitonic sort (dynamic pow2 size) ----------------
__global__ void k_sort() {
    int b = blockIdx.x;
    int tid = threadIdx.x;
    __shared__ unsigned long long sk[KNMS];
    int cnt = g_cntW[b]; if (cnt > KNMS) cnt = KNMS;
    int S = 1024;
    while (S < cnt) S <<= 1;     // S in {1024, 2048, 4096}
    for (int t = tid; t < S; t += 1024)
        sk[t] = (t < cnt) ? g_key[b * KNMS + t] : 0ull;
    __syncthreads();
    for (int k = 2; k <= S; k <<= 1) {
        for (int j = k >> 1; j > 0; j >>= 1) {
            for (int t = tid; t < S; t += 1024) {
                int l = t ^ j;
                if (l > t) {
                    unsigned long long a = sk[t], c = sk[l];
                    bool up = (t & k) == 0;
                    bool sw = up ? (a < c) : (a > c);
                    if (sw) { sk[t] = c; sk[l] = a; }
                }
            }
            __syncthreads();
        }
    }
    for (int t = tid; t < cnt; t += 1024) {
        unsigned long long key = sk[t];
        unsigned m = ~(unsigned)key;
        g_sm[b * KNMS + t] = (int)m;
        float4 bx = g_bx[b * KNMS + m];
        g_sx1[b * KNMS + t] = bx.x;
        g_sy1[b * KNMS + t] = bx.y;
        g_sx2[b * KNMS + t] = bx.z;
        g_sy2[b * KNMS + t] = bx.w;
    }
}

// ---------------- K5: per-class greedy NMS + cap 1000 + output ----------------
// Classes never overlap (offset 7680 >> max box extent), so cross-class IoU is
// exactly 0.0f and the global greedy decomposes into 80 per-class chains.
__global__ void k_nms(const float* __restrict__ p, float* __restrict__ out) {
    int b = blockIdx.x;
    int tid = threadIdx.x, lane = tid & 31, wid = tid >> 5;

    extern __shared__ int idyn[];
    float* sx1 = (float*)idyn;              // 4096
    float* sy1 = sx1 + KNMS;
    float* sx2 = sy1 + KNMS;
    float* sy2 = sx2 + KNMS;
    float* sar = sy2 + KNMS;
    int*   picks = idyn + 5 * KNMS;         // 1024
    unsigned short* lists = (unsigned short*)(idyn + 5 * KNMS + 1024); // 32*256 u16
    unsigned char* scl   = (unsigned char*)(idyn + 5 * KNMS + 1024 + 4096);
    unsigned char* keepf = (unsigned char*)(idyn + 5 * KNMS + 1024 + 4096 + 1024);
    __shared__ int wsum[32];
    __shared__ int s_total;
    __shared__ float s_out[NCL];

    int C = g_cntW[b]; if (C > KNMS) C = KNMS;

    for (int t = tid; t < KNMS; t += 1024) keepf[t] = 0;
    for (int t = tid; t < C; t += 1024) {
        float x1 = g_sx1[b * KNMS + t];
        float y1 = g_sy1[b * KNMS + t];
        float x2 = g_sx2[b * KNMS + t];
        float y2 = g_sy2[b * KNMS + t];
        sx1[t] = x1; sy1[t] = y1; sx2[t] = x2; sy2[t] = y2;
        sar[t] = __fmul_rn(__fsub_rn(x2, x1), __fsub_rn(y2, y1));
        scl[t] = (unsigned char)__float2int_rn(x1 * (1.0f / MAXWH));
    }
    if (tid < NCL) s_out[tid] = 0.0f;
    __syncthreads();

    // per-class greedy: warp wid handles classes wid, wid+32, wid+64
    for (int c = wid; c < NCL; c += 32) {
        unsigned short* lst = lists + wid * CLCAP;
        int n = 0;
        for (int base = 0; base < C; base += 32) {
            int t = base + lane;
            bool m = (t < C) && (scl[t] == (unsigned char)c);
            unsigned bal = __ballot_sync(FULLM, m);
            if (m) {
                int pos = n + __popc(bal & ((1u << lane) - 1u));
                if (pos < CLCAP) lst[pos] = (unsigned short)t;
            }
            n += __popc(bal);
        }
        if (n > CLCAP) n = CLCAP;

        unsigned rm = 0;  // removed bits: entry e owned by lane e&31, bit e>>5
        for (int i = 0; i < n; i++) {
            unsigned rmi = __shfl_sync(FULLM, rm, i & 31);
            if ((rmi >> (i >> 5)) & 1u) continue;   // uniform
            int ti = lst[i];
            if (lane == 0) keepf[ti] = 1;
            float bx1 = sx1[ti], by1 = sy1[ti], bx2 = sx2[ti], by2 = sy2[ti];
            float ba = sar[ti];
            for (int k = 0, e = lane; e < n; k++, e += 32) {
                if (e > i && !((rm >> k) & 1u)) {
                    int tj = lst[e];
                    float iw = __fsub_rn(fminf(sx2[tj], bx2), fmaxf(sx1[tj], bx1));
                    float ih = __fsub_rn(fminf(sy2[tj], by2), fmaxf(sy1[tj], by1));
                    float inter = __fmul_rn(fmaxf(iw, 0.0f), fmaxf(ih, 0.0f));
                    float denom = __fsub_rn(__fadd_rn(sar[tj], ba), inter);
                    if (__fdiv_rn(inter, denom) > IOU_T) rm |= (1u << k);
                }
            }
            __syncwarp();
        }
    }
    __syncthreads();

    // block prefix-scan over keep flags (4/thread), cap at MAXDET
    int t0 = tid * 4;
    int k0 = keepf[t0], k1 = keepf[t0 + 1], k2 = keepf[t0 + 2], k3 = keepf[t0 + 3];
    int sum4 = k0 + k1 + k2 + k3;
    int s = sum4;
    for (int o = 1; o < 32; o <<= 1) {
        int v = __shfl_up_sync(FULLM, s, o);
        if (lane >= o) s += v;
    }
    if (lane == 31) wsum[wid] = s;
    __syncthreads();
    if (wid == 0) {
        int w = wsum[lane];
        for (int o = 1; o < 32; o <<= 1) {
            int v = __shfl_up_sync(FULLM, w, o);
            if (lane >= o) w += v;
        }
        wsum[lane] = w;
        if (lane == 31) s_total = w;
    }
    __syncthreads();
    int base = (wid ? wsum[wid - 1] : 0) + (s - sum4);
    int p0 = base + k0;
    int p1 = p0 + k1;
    int p2 = p1 + k2;
    int p3 = p2 + k3;
    if (k0 && p0 <= MAXDET) picks[p0 - 1] = g_sm[b * KNMS + t0];
    if (k1 && p1 <= MAXDET) picks[p1 - 1] = g_sm[b * KNMS + t0 + 1];
    if (k2 && p2 <= MAXDET) picks[p2 - 1] = g_sm[b * KNMS + t0 + 2];
    if (k3 && p3 <= MAXDET) picks[p3 - 1] = g_sm[b * KNMS + t0 + 3];
    __syncthreads();

    // warp-per-pick coalesced accumulation: lane owns cls {lane, lane+32, lane+64}
    int cnt = s_total; if (cnt > MAXDET) cnt = MAXDET;
    float a0 = 0.0f, a1 = 0.0f, a2 = 0.0f;
    for (int t = wid; t < cnt; t += 32) {
        int m = picks[t];
        int rowi = g_A[b * NN + m];            // reference's idx1[order] "pick"
        const float* pr = p + ((size_t)b * NN + rowi) * NCH;
        float obj = pr[4];
        a0 += obj * pr[5 + lane];              // cls 0..31
        a1 += obj * pr[37 + lane];             // cls 32..63
        if (lane < 16) a2 += obj * pr[69 + lane];  // cls 64..79
    }
    atomicAdd(&s_out[lane], a0);
    atomicAdd(&s_out[32 + lane], a1);
    if (lane < 16) atomicAdd(&s_out[64 + lane], a2);
    __syncthreads();
    if (tid < NCL) out[b * NCL + tid] = s_out[tid];
}

// ---------------- launcher ----------------
extern "C" void kernel_launch(void* const* d_in, const int* in_sizes, int n_in,
                              void* d_out, int out_size) {
    const float* p = (const float*)d_in[0];
    float* out = (float*)d_out;

    k_compactA<<<BB, 1024>>>(p);
    k_cand<<<dim3(192, BB), 256>>>(p);
    k_compactW<<<BB, 1024>>>();
    k_sort<<<BB, 1024>>>();
    int smem = (5 * KNMS + 1024 + 4096 + 1024 + 1024) * 4;
    cudaFuncSetAttribute(k_nms, cudaFuncAttributeMaxDynamicSharedMemorySize, smem);
    k_nms<<<BB, 1024, smem>>>(p, out);
}

// round 4
// speedup vs baseline: 7.8392x; 1.1232x over previous
#include <cuda_runtime.h>
#include <cstdint>

#define BB   32
#define NN   25200
#define NCH  85
#define NCL  80
#define KNMS 4096
#define CONF_T 0.25f
#define IOU_T  0.45f
#define MAXDET 1000
#define MAXWH  7680.0f
#define NWORDS 788          // ceil(25200/32)
#define CLCAP 256
#define FULLM 0xffffffffu

__device__ unsigned g_mask[BB * NWORDS];

// ---------------- K1: obj-only read -> xc bitmask ----------------
__global__ void k_mask(const float* __restrict__ p) {
    int b = blockIdx.y;
    int r = blockIdx.x * blockDim.x + threadIdx.x;
    bool xc = false;
    if (r < NN) xc = p[((size_t)b * NN + r) * NCH + 4] > CONF_T;
    unsigned bal = __ballot_sync(FULLM, xc);
    if ((threadIdx.x & 31) == 0 && r < NN)
        g_mask[b * NWORDS + (r >> 5)] = bal;
}

// ---------------- K2: fully fused per-image pipeline ----------------
__global__ void k_fused(const float* __restrict__ p, float* __restrict__ out) {
    int b = blockIdx.x;
    int tid = threadIdx.x, lane = tid & 31, wid = tid >> 5;

    extern __shared__ char smem[];
    float*          sx1   = (float*)(smem + 0);          // by w-rank m
    float*          sy1   = (float*)(smem + 16384);
    float*          sx2   = (float*)(smem + 32768);
    float*          sy2   = (float*)(smem + 49152);
    float*          sar   = (float*)(smem + 65536);
    unsigned long long* keys = (unsigned long long*)(smem + 81920);  // 8-aligned
    unsigned short* perm  = (unsigned short*)(smem + 114688); // sorted pos t -> m
    unsigned short* A     = (unsigned short*)(smem + 122880); // xc rank -> row
    unsigned short* wr2a  = (unsigned short*)(smem + 131072); // w-rank m -> xc rank i
    float*          cconf = (float*)(smem + 139264);
    unsigned char*  cj    = (unsigned char*)(smem + 155648);
    unsigned char*  cw    = (unsigned char*)(smem + 159744);
    unsigned char*  scls  = (unsigned char*)(smem + 163840); // class by sorted pos t
    unsigned char*  keepf = (unsigned char*)(smem + 167936);
    unsigned*       lists = (unsigned*)(smem + 172032);      // 32 warps * 256 : (t<<16)|m
    int*            picks = (int*)(smem + 204800);
    __shared__ int wsum[32];
    __shared__ int s_cntA, s_cntW, s_total;
    __shared__ float s_out[NCL];

    // ---- phase 1: bitmask -> stable A list (block scan over 788 words) ----
    unsigned myword = 0; int mycnt = 0;
    if (tid < NWORDS) { myword = g_mask[b * NWORDS + tid]; mycnt = __popc(myword); }
    int s = mycnt;
    for (int o = 1; o < 32; o <<= 1) {
        int v = __shfl_up_sync(FULLM, s, o);
        if (lane >= o) s += v;
    }
    if (lane == 31) wsum[wid] = s;
    __syncthreads();
    if (wid == 0) {
        int w = wsum[lane];
        for (int o = 1; o < 32; o <<= 1) {
            int v = __shfl_up_sync(FULLM, w, o);
            if (lane >= o) w += v;
        }
        wsum[lane] = w;
        if (lane == 31) s_cntA = w;
    }
    __syncthreads();
    int excl = (wid ? wsum[wid - 1] : 0) + s - mycnt;
    if (tid < NWORDS) {
        unsigned w = myword; int pos = excl;
        while (w) {
            int bit = __ffs(w) - 1; w &= w - 1;
            if (pos < KNMS) A[pos] = (unsigned short)(tid * 32 + bit);
            pos++;
        }
    }
    if (tid < NCL) s_out[tid] = 0.0f;
    for (int t = tid; t < KNMS; t += 1024) keepf[t] = 0;
    __syncthreads();
    int cntA = s_cntA; if (cntA > KNMS) cntA = KNMS;

    // ---- phase 2: candidate scoring (warp per candidate) ----
    for (int i = wid; i < cntA; i += 32) {
        const float* pr = p + ((size_t)b * NN + A[i]) * NCH;
        float v0 = pr[lane];
        float v1 = pr[lane + 32];
        float v2 = (lane < 21) ? pr[lane + 64] : 0.0f;
        float obj = __shfl_sync(FULLM, v0, 4);

        float bv = -3.4e38f; int bi = 1 << 20;
        if (lane >= 5) { bv = obj * v0; bi = lane - 5; }          // cls 0..26
        { float sc = obj * v1; int i1 = lane + 27;                // cls 27..58
          if (sc > bv) { bv = sc; bi = i1; } }
        if (lane < 21) { float sc = obj * v2; int i2 = lane + 59; // cls 59..79
          if (sc > bv) { bv = sc; bi = i2; } }
        for (int off = 16; off; off >>= 1) {
            float ov = __shfl_xor_sync(FULLM, bv, off);
            int   oi = __shfl_xor_sync(FULLM, bi, off);
            if (ov > bv || (ov == bv && oi < bi)) { bv = ov; bi = oi; }
        }
        if (lane == 0) {
            cconf[i] = bv;
            cj[i] = (unsigned char)bi;
            cw[i] = (bv > CONF_T) ? 1 : 0;
        }
    }
    __syncthreads();

    // ---- phase 3: stable w-compaction (ordered, thread-strided) ----
    if (tid == 0) s_cntW = 0;
    __syncthreads();
    for (int base = 0; base < cntA; base += 1024) {
        int i = base + tid;
        bool w = (i < cntA) && cw[i];
        unsigned mW = __ballot_sync(FULLM, w);
        if (lane == 0) wsum[wid] = __popc(mW);
        __syncthreads();
        int pre = 0;
        for (int w2 = 0; w2 < wid; w2++) pre += wsum[w2];
        if (w) {
            int pos = s_cntW + pre + __popc(mW & ((1u << lane) - 1u));
            if (pos < KNMS) {
                wr2a[pos] = (unsigned short)i;
                keys[pos] = ((unsigned long long)__float_as_uint(cconf[i]) << 32)
                          | (unsigned long long)(~(unsigned)pos);
            }
        }
        __syncthreads();
        if (tid == 0) {
            int tot = 0;
            for (int w2 = 0; w2 < 32; w2++) tot += wsum[w2];
            s_cntW += tot;
        }
        __syncthreads();
    }
    int C = s_cntW; if (C > KNMS) C = KNMS;

    // ---- phase 4: build boxes by w-rank ----
    for (int m = tid; m < C; m += 1024) {
        int i = wr2a[m];
        const float* pr = p + ((size_t)b * NN + A[i]) * NCH;
        float x = pr[0], y = pr[1], ww = pr[2], hh = pr[3];
        float off = (float)cj[i] * MAXWH;
        float hw = __fmul_rn(ww, 0.5f);
        float hv = __fmul_rn(hh, 0.5f);
        float x1 = __fadd_rn(__fsub_rn(x, hw), off);
        float y1 = __fadd_rn(__fsub_rn(y, hv), off);
        float x2 = __fadd_rn(__fadd_rn(x, hw), off);
        float y2 = __fadd_rn(__fadd_rn(y, hv), off);
        sx1[m] = x1; sy1[m] = y1; sx2[m] = x2; sy2[m] = y2;
        sar[m] = __fmul_rn(__fsub_rn(x2, x1), __fsub_rn(y2, y1));
    }
    // ---- phase 5: bitonic sort of keys (dynamic pow2) ----
    int S = 1024;
    while (S < C) S <<= 1;                 // 1024/2048/4096
    for (int t = tid; t < S; t += 1024)
        if (t >= C) keys[t] = 0ull;
    __syncthreads();
    for (int k = 2; k <= S; k <<= 1) {
        for (int j = k >> 1; j > 0; j >>= 1) {
            for (int t = tid; t < S; t += 1024) {
                int l = t ^ j;
                if (l > t) {
                    unsigned long long a = keys[t], c2 = keys[l];
                    bool up = (t & k) == 0;
                    bool sw = up ? (a < c2) : (a > c2);
                    if (sw) { keys[t] = c2; keys[l] = a; }
                }
            }
            __syncthreads();
        }
    }
    for (int t = tid; t < C; t += 1024) {
        unsigned m = ~(unsigned)keys[t];
        perm[t] = (unsigned short)m;
        scls[t] = cj[wr2a[m]];
    }
    __syncthreads();

    // ---- phase 6: per-class greedy NMS (classes never overlap: offset 7680) ----
    for (int c = wid; c < NCL; c += 32) {
        unsigned* lst = lists + wid * CLCAP;
        int n = 0;
        for (int base = 0; base < C; base += 32) {
            int t = base + lane;
            bool m = (t < C) && (scls[t] == (unsigned char)c);
            unsigned bal = __ballot_sync(FULLM, m);
            if (m) {
                int pos = n + __popc(bal & ((1u << lane) - 1u));
                if (pos < CLCAP)
                    lst[pos] = ((unsigned)t << 16) | (unsigned)perm[t];
            }
            n += __popc(bal);
        }
        if (n > CLCAP) n = CLCAP;

        unsigned rm = 0;  // removed: entry e owned by lane e&31, bit e>>5
        for (int i = 0; i < n; i++) {
            unsigned rmi = __shfl_sync(FULLM, rm, i & 31);
            if ((rmi >> (i >> 5)) & 1u) continue;   // uniform
            unsigned ei = lst[i];
            int mi = ei & 0xffff;
            if (lane == 0) keepf[ei >> 16] = 1;
            float bx1 = sx1[mi], by1 = sy1[mi], bx2 = sx2[mi], by2 = sy2[mi];
            float ba = sar[mi];
            for (int k = 0, e = lane; e < n; k++, e += 32) {
                if (e > i && !((rm >> k) & 1u)) {
                    int mj = lst[e] & 0xffff;
                    float iw = __fsub_rn(fminf(sx2[mj], bx2), fmaxf(sx1[mj], bx1));
                    float ih = __fsub_rn(fminf(sy2[mj], by2), fmaxf(sy1[mj], by1));
                    float inter = __fmul_rn(fmaxf(iw, 0.0f), fmaxf(ih, 0.0f));
                    float denom = __fsub_rn(__fadd_rn(sar[mj], ba), inter);
                    if (__fdiv_rn(inter, denom) > IOU_T) rm |= (1u << k);
                }
            }
            __syncwarp();
        }
    }
    __syncthreads();

    // ---- phase 7: prefix over keep flags (4/thread), cap MAXDET, picks ----
    int t0 = tid * 4;
    int k0 = keepf[t0], k1 = keepf[t0 + 1], k2 = keepf[t0 + 2], k3 = keepf[t0 + 3];
    int sum4 = k0 + k1 + k2 + k3;
    int sc = sum4;
    for (int o = 1; o < 32; o <<= 1) {
        int v = __shfl_up_sync(FULLM, sc, o);
        if (lane >= o) sc += v;
    }
    if (lane == 31) wsum[wid] = sc;
    __syncthreads();
    if (wid == 0) {
        int w = wsum[lane];
        for (int o = 1; o < 32; o <<= 1) {
            int v = __shfl_up_sync(FULLM, w, o);
            if (lane >= o) w += v;
        }
        wsum[lane] = w;
        if (lane == 31) s_total = w;
    }
    __syncthreads();
    int base2 = (wid ? wsum[wid - 1] : 0) + (sc - sum4);
    int p0 = base2 + k0, p1 = p0 + k1, p2 = p1 + k2, p3 = p2 + k3;
    if (k0 && p0 <= MAXDET) picks[p0 - 1] = perm[t0];
    if (k1 && p1 <= MAXDET) picks[p1 - 1] = perm[t0 + 1];
    if (k2 && p2 <= MAXDET) picks[p2 - 1] = perm[t0 + 2];
    if (k3 && p3 <= MAXDET) picks[p3 - 1] = perm[t0 + 3];
    __syncthreads();

    // ---- phase 8: accumulation (warp per pick; reference's A[m] pick quirk) ----
    int cnt = s_total; if (cnt > MAXDET) cnt = MAXDET;
    float a0 = 0.0f, a1 = 0.0f, a2 = 0.0f;
    for (int t = wid; t < cnt; t += 32) {
        int m = picks[t];
        const float* pr = p + ((size_t)b * NN + A[m]) * NCH;
        float obj = pr[4];
        a0 += obj * pr[5 + lane];                   // cls 0..31
        a1 += obj * pr[37 + lane];                  // cls 32..63
        if (lane < 16) a2 += obj * pr[69 + lane];   // cls 64..79
    }
    atomicAdd(&s_out[lane], a0);
    atomicAdd(&s_out[32 + lane], a1);
    if (lane < 16) atomicAdd(&s_out[64 + lane], a2);
    __syncthreads();
    if (tid < NCL) out[b * NCL + tid] = s_out[tid];
}

// ---------------- launcher ----------------
extern "C" void kernel_launch(void* const* d_in, const int* in_sizes, int n_in,
                              void* d_out, int out_size) {
    const float* p = (const float*)d_in[0];
    float* out = (float*)d_out;

    k_mask<<<dim3((NN + 255) / 256, BB), 256>>>(p);
    int smem = 208896;
    cudaFuncSetAttribute(k_fused, cudaFuncAttributeMaxDynamicSharedMemorySize, smem);
    k_fused<<<BB, 1024, smem>>>(p, out);
}

// round 5
// speedup vs baseline: 9.5118x; 1.2134x over previous
#include <cuda_runtime.h>
#include <cstdint>

#define BB   32
#define NN   25200
#define NCH  85
#define NCL  80
#define KNMS 4096
#define CONF_T 0.25f
#define IOU_T  0.45f
#define MAXDET 1000
#define MAXWH  7680.0f
#define CLCAP 256
#define FULLM 0xffffffffu
#define RPB  256           // rows per k_all block
#define RPT  25            // rows per thread in k_fused scan (1024*25 >= 25200)

__device__ unsigned char g_flags[BB * NN];   // bit0 xc, bit1 w (written for EVERY row each launch)
__device__ float         g_conf[BB * NN];    // by row (xc rows only)
__device__ unsigned char g_j[BB * NN];       // by row
__device__ float4        g_cbox[BB * NN];    // by row (w rows only)

// ---------------- K1: full-grid row scan + candidate scoring ----------------
__global__ void k_all(const float* __restrict__ p) {
    int b = blockIdx.y;
    int r0 = blockIdx.x * RPB;
    int tid = threadIdx.x, lane = tid & 31, wid = tid >> 5;
    __shared__ unsigned short wl[RPB];
    __shared__ int s_cnt;
    if (tid == 0) s_cnt = 0;
    __syncthreads();

    int row = r0 + tid;
    bool xc = false;
    if (row < NN) {
        float obj = p[((size_t)b * NN + row) * NCH + 4];
        xc = obj > CONF_T;
        g_flags[b * NN + row] = xc ? 1 : 0;
    }
    unsigned bal = __ballot_sync(FULLM, xc);
    int base = 0;
    if (lane == 0 && bal) base = atomicAdd(&s_cnt, __popc(bal));
    base = __shfl_sync(FULLM, base, 0);
    if (xc) wl[base + __popc(bal & ((1u << lane) - 1u))] = (unsigned short)row;
    __syncthreads();

    int cnt = s_cnt;
    for (int k = wid; k < cnt; k += 8) {
        int r = wl[k];
        const float* pr = p + ((size_t)b * NN + r) * NCH;
        float v0 = pr[lane];
        float v1 = pr[lane + 32];
        float v2 = (lane < 21) ? pr[lane + 64] : 0.0f;
        float obj = __shfl_sync(FULLM, v0, 4);

        float bv = -3.4e38f; int bi = 1 << 20;
        if (lane >= 5) { bv = obj * v0; bi = lane - 5; }          // cls 0..26
        { float sc = obj * v1; int i1 = lane + 27;                // cls 27..58
          if (sc > bv) { bv = sc; bi = i1; } }
        if (lane < 21) { float sc = obj * v2; int i2 = lane + 59; // cls 59..79
          if (sc > bv) { bv = sc; bi = i2; } }
        for (int off = 16; off; off >>= 1) {
            float ov = __shfl_xor_sync(FULLM, bv, off);
            int   oi = __shfl_xor_sync(FULLM, bi, off);
            if (ov > bv || (ov == bv && oi < bi)) { bv = ov; bi = oi; }
        }
        float x  = __shfl_sync(FULLM, v0, 0);
        float y  = __shfl_sync(FULLM, v0, 1);
        float ww = __shfl_sync(FULLM, v0, 2);
        float hh = __shfl_sync(FULLM, v0, 3);
        if (lane == 0) {
            g_conf[b * NN + r] = bv;
            g_j[b * NN + r] = (unsigned char)bi;
            if (bv > CONF_T) {
                g_flags[b * NN + r] = 3;
                float off = (float)bi * MAXWH;
                float hw = __fmul_rn(ww, 0.5f);
                float hv = __fmul_rn(hh, 0.5f);
                float4 bx;
                bx.x = __fadd_rn(__fsub_rn(x, hw), off);
                bx.y = __fadd_rn(__fsub_rn(y, hv), off);
                bx.z = __fadd_rn(__fadd_rn(x, hw), off);
                bx.w = __fadd_rn(__fadd_rn(y, hv), off);
                g_cbox[b * NN + r] = bx;
            }
        }
    }
}

// ---------------- K2: per-image serial core ----------------
__global__ void k_fused(const float* __restrict__ p, float* __restrict__ out) {
    int b = blockIdx.x;
    int tid = threadIdx.x, lane = tid & 31, wid = tid >> 5;

    extern __shared__ char smem[];
    unsigned long long* keys = (unsigned long long*)(smem + 0);        // 32KB
    float*          sx1   = (float*)(smem + 32768);
    float*          sy1   = (float*)(smem + 49152);
    float*          sx2   = (float*)(smem + 65536);
    float*          sy2   = (float*)(smem + 81920);
    float*          sar   = (float*)(smem + 98304);
    unsigned*       lists = (unsigned*)(smem + 114688);                // 32KB
    int*            picks = (int*)(smem + 147456);                     // 4KB
    unsigned short* perm  = (unsigned short*)(smem + 151552);          // 8KB
    unsigned short* A     = (unsigned short*)(smem + 159744);          // 8KB
    unsigned short* wrow  = (unsigned short*)(smem + 167936);          // 8KB
    unsigned char*  scb   = (unsigned char*)(smem + 176128);           // class by m
    unsigned char*  scls  = (unsigned char*)(smem + 180224);           // class by sorted t
    unsigned char*  keepf = (unsigned char*)(smem + 184320);
    __shared__ int wsum[32];
    __shared__ int s_total;
    __shared__ float s_out[NCL];

    const unsigned char* fl = g_flags + (size_t)b * NN;

    // ---- phase 1: dual order-preserving compaction (one packed block scan) ----
    int start = tid * RPT;
    int myA = 0, myW = 0;
    #pragma unroll
    for (int k = 0; k < RPT; k++) {
        int r = start + k;
        unsigned char f = (r < NN) ? fl[r] : 0;
        myA += f & 1; myW += f >> 1;
    }
    int pk = myA | (myW << 16);
    int s = pk;
    for (int o = 1; o < 32; o <<= 1) {
        int v = __shfl_up_sync(FULLM, s, o);
        if (lane >= o) s += v;
    }
    if (lane == 31) wsum[wid] = s;
    __syncthreads();
    if (wid == 0) {
        int w = wsum[lane];
        for (int o = 1; o < 32; o <<= 1) {
            int v = __shfl_up_sync(FULLM, w, o);
            if (lane >= o) w += v;
        }
        wsum[lane] = w;
        if (lane == 31) s_total = w;
    }
    __syncthreads();
    int excl = (wid ? wsum[wid - 1] : 0) + s - pk;
    int pa = excl & 0xffff;
    int pw = excl >> 16;
    #pragma unroll
    for (int k = 0; k < RPT; k++) {
        int r = start + k;
        unsigned char f = (r < NN) ? fl[r] : 0;
        if (f & 1) { if (pa < KNMS) A[pa] = (unsigned short)r; pa++; }
        if (f & 2) { if (pw < KNMS) wrow[pw] = (unsigned short)r; pw++; }
    }
    int tot = s_total;
    int cntW = tot >> 16; if (cntW > KNMS) cntW = KNMS;
    int C = cntW;
    if (tid < NCL) s_out[tid] = 0.0f;
    for (int t = tid; t < KNMS; t += 1024) keepf[t] = 0;
    __syncthreads();

    // ---- phase 2: keys + boxes by w-rank ----
    for (int m = tid; m < C; m += 1024) {
        int r = wrow[m];
        keys[m] = ((unsigned long long)__float_as_uint(g_conf[b * NN + r]) << 32)
                | (unsigned long long)(~(unsigned)m);
        float4 bx = g_cbox[b * NN + r];
        sx1[m] = bx.x; sy1[m] = bx.y; sx2[m] = bx.z; sy2[m] = bx.w;
        sar[m] = __fmul_rn(__fsub_rn(bx.z, bx.x), __fsub_rn(bx.w, bx.y));
        scb[m] = g_j[b * NN + r];
    }
    // ---- phase 3: bitonic sort (dynamic pow2) ----
    int S = 1024;
    while (S < C) S <<= 1;
    for (int t = tid; t < S; t += 1024)
        if (t >= C) keys[t] = 0ull;
    __syncthreads();
    for (int k = 2; k <= S; k <<= 1) {
        for (int j = k >> 1; j > 0; j >>= 1) {
            for (int t = tid; t < S; t += 1024) {
                int l = t ^ j;
                if (l > t) {
                    unsigned long long a = keys[t], c2 = keys[l];
                    bool up = (t & k) == 0;
                    bool sw = up ? (a < c2) : (a > c2);
                    if (sw) { keys[t] = c2; keys[l] = a; }
                }
            }
            __syncthreads();
        }
    }
    for (int t = tid; t < C; t += 1024) {
        unsigned m = ~(unsigned)keys[t];
        perm[t] = (unsigned short)m;
        scls[t] = scb[m];
    }
    __syncthreads();

    // ---- phase 4: per-class warp greedy (classes never overlap: offset 7680) ----
    for (int c = wid; c < NCL; c += 32) {
        unsigned* lst = lists + wid * CLCAP;
        int n = 0;
        for (int base = 0; base < C; base += 32) {
            int t = base + lane;
            bool m = (t < C) && (scls[t] == (unsigned char)c);
            unsigned bal = __ballot_sync(FULLM, m);
            if (m) {
                int pos = n + __popc(bal & ((1u << lane) - 1u));
                if (pos < CLCAP)
                    lst[pos] = ((unsigned)t << 16) | (unsigned)perm[t];
            }
            n += __popc(bal);
        }
        if (n > CLCAP) n = CLCAP;

        unsigned rm = 0;
        for (int i = 0; i < n; i++) {
            unsigned rmi = __shfl_sync(FULLM, rm, i & 31);
            if ((rmi >> (i >> 5)) & 1u) continue;
            unsigned ei = lst[i];
            int mi = ei & 0xffff;
            if (lane == 0) keepf[ei >> 16] = 1;
            float bx1 = sx1[mi], by1 = sy1[mi], bx2 = sx2[mi], by2 = sy2[mi];
            float ba = sar[mi];
            for (int k = 0, e = lane; e < n; k++, e += 32) {
                if (e > i && !((rm >> k) & 1u)) {
                    int mj = lst[e] & 0xffff;
                    float iw = __fsub_rn(fminf(sx2[mj], bx2), fmaxf(sx1[mj], bx1));
                    float ih = __fsub_rn(fminf(sy2[mj], by2), fmaxf(sy1[mj], by1));
                    float inter = __fmul_rn(fmaxf(iw, 0.0f), fmaxf(ih, 0.0f));
                    float denom = __fsub_rn(__fadd_rn(sar[mj], ba), inter);
                    if (__fdiv_rn(inter, denom) > IOU_T) rm |= (1u << k);
                }
            }
            __syncwarp();
        }
    }
    __syncthreads();

    // ---- phase 5: prefix over keep flags, cap MAXDET ----
    int t0 = tid * 4;
    int k0 = keepf[t0], k1 = keepf[t0 + 1], k2 = keepf[t0 + 2], k3 = keepf[t0 + 3];
    int sum4 = k0 + k1 + k2 + k3;
    int sc = sum4;
    for (int o = 1; o < 32; o <<= 1) {
        int v = __shfl_up_sync(FULLM, sc, o);
        if (lane >= o) sc += v;
    }
    if (lane == 31) wsum[wid] = sc;
    __syncthreads();
    if (wid == 0) {
        int w = wsum[lane];
        for (int o = 1; o < 32; o <<= 1) {
            int v = __shfl_up_sync(FULLM, w, o);
            if (lane >= o) w += v;
        }
        wsum[lane] = w;
        if (lane == 31) s_total = w;
    }
    __syncthreads();
    int base2 = (wid ? wsum[wid - 1] : 0) + (sc - sum4);
    int p0 = base2 + k0, p1 = p0 + k1, p2 = p1 + k2, p3 = p2 + k3;
    if (k0 && p0 <= MAXDET) picks[p0 - 1] = perm[t0];
    if (k1 && p1 <= MAXDET) picks[p1 - 1] = perm[t0 + 1];
    if (k2 && p2 <= MAXDET) picks[p2 - 1] = perm[t0 + 2];
    if (k3 && p3 <= MAXDET) picks[p3 - 1] = perm[t0 + 3];
    __syncthreads();

    // ---- phase 6: accumulation (warp per pick; reference's A[m] pick quirk) ----
    int cnt = s_total; if (cnt > MAXDET) cnt = MAXDET;
    float a0 = 0.0f, a1 = 0.0f, a2 = 0.0f;
    for (int t = wid; t < cnt; t += 32) {
        int m = picks[t];
        const float* pr = p + ((size_t)b * NN + A[m]) * NCH;
        float obj = pr[4];
        a0 += obj * pr[5 + lane];
        a1 += obj * pr[37 + lane];
        if (lane < 16) a2 += obj * pr[69 + lane];
    }
    atomicAdd(&s_out[lane], a0);
    atomicAdd(&s_out[32 + lane], a1);
    if (lane < 16) atomicAdd(&s_out[64 + lane], a2);
    __syncthreads();
    if (tid < NCL) out[b * NCL + tid] = s_out[tid];
}

// ---------------- launcher ----------------
extern "C" void kernel_launch(void* const* d_in, const int* in_sizes, int n_in,
                              void* d_out, int out_size) {
    const float* p = (const float*)d_in[0];
    float* out = (float*)d_out;

    k_all<<<dim3((NN + RPB - 1) / RPB, BB), RPB>>>(p);
    int smem = 188416;
    cudaFuncSetAttribute(k_fused, cudaFuncAttributeMaxDynamicSharedMemorySize, smem);
    k_fused<<<BB, 1024, smem>>>(p, out);
}

// round 6
// speedup vs baseline: 10.7428x; 1.1294x over previous
#include <cuda_runtime.h>
#include <cstdint>

#define BB   32
#define NN   25200
#define NCH  85
#define NCL  80
#define KNMS 4096
#define CONF_T 0.25f
#define IOU_T  0.45f
#define MAXDET 1000
#define MAXWH  7680.0f
#define CLCAP 256
#define FULLM 0xffffffffu
#define RPB  256           // rows per k_all block
#define RPT  25            // rows per thread in k_fused scan (1024*25 >= 25200)

__device__ unsigned char g_flags[BB * NN];   // bit0 xc, bit1 w (written for EVERY row each launch)
__device__ float         g_conf[BB * NN];    // by row (xc rows only)
__device__ unsigned char g_j[BB * NN];       // by row
__device__ float4        g_cbox[BB * NN];    // by row (w rows only)

// ---------------- K1: full-grid row scan + candidate scoring ----------------
__global__ void k_all(const float* __restrict__ p) {
    int b = blockIdx.y;
    int r0 = blockIdx.x * RPB;
    int tid = threadIdx.x, lane = tid & 31, wid = tid >> 5;
    __shared__ unsigned short wl[RPB];
    __shared__ int s_cnt;
    if (tid == 0) s_cnt = 0;
    __syncthreads();

    int row = r0 + tid;
    bool xc = false;
    if (row < NN) {
        float obj = p[((size_t)b * NN + row) * NCH + 4];
        xc = obj > CONF_T;
        g_flags[b * NN + row] = xc ? 1 : 0;
    }
    unsigned bal = __ballot_sync(FULLM, xc);
    int base = 0;
    if (lane == 0 && bal) base = atomicAdd(&s_cnt, __popc(bal));
    base = __shfl_sync(FULLM, base, 0);
    if (xc) wl[base + __popc(bal & ((1u << lane) - 1u))] = (unsigned short)row;
    __syncthreads();

    int cnt = s_cnt;
    for (int k = wid; k < cnt; k += 8) {
        int r = wl[k];
        const float* pr = p + ((size_t)b * NN + r) * NCH;
        float v0 = pr[lane];
        float v1 = pr[lane + 32];
        float v2 = (lane < 21) ? pr[lane + 64] : 0.0f;
        float obj = __shfl_sync(FULLM, v0, 4);

        float bv = -3.4e38f; int bi = 1 << 20;
        if (lane >= 5) { bv = obj * v0; bi = lane - 5; }          // cls 0..26
        { float sc = obj * v1; int i1 = lane + 27;                // cls 27..58
          if (sc > bv) { bv = sc; bi = i1; } }
        if (lane < 21) { float sc = obj * v2; int i2 = lane + 59; // cls 59..79
          if (sc > bv) { bv = sc; bi = i2; } }
        for (int off = 16; off; off >>= 1) {
            float ov = __shfl_xor_sync(FULLM, bv, off);
            int   oi = __shfl_xor_sync(FULLM, bi, off);
            if (ov > bv || (ov == bv && oi < bi)) { bv = ov; bi = oi; }
        }
        float x  = __shfl_sync(FULLM, v0, 0);
        float y  = __shfl_sync(FULLM, v0, 1);
        float ww = __shfl_sync(FULLM, v0, 2);
        float hh = __shfl_sync(FULLM, v0, 3);
        if (lane == 0) {
            g_conf[b * NN + r] = bv;
            g_j[b * NN + r] = (unsigned char)bi;
            if (bv > CONF_T) {
                g_flags[b * NN + r] = 3;
                float off = (float)bi * MAXWH;
                float hw = __fmul_rn(ww, 0.5f);
                float hv = __fmul_rn(hh, 0.5f);
                float4 bx;
                bx.x = __fadd_rn(__fsub_rn(x, hw), off);
                bx.y = __fadd_rn(__fsub_rn(y, hv), off);
                bx.z = __fadd_rn(__fadd_rn(x, hw), off);
                bx.w = __fadd_rn(__fadd_rn(y, hv), off);
                g_cbox[b * NN + r] = bx;
            }
        }
    }
}

// ---------------- K2: per-image serial core (no global sort) ----------------
__global__ void k_fused(const float* __restrict__ p, float* __restrict__ out) {
    int b = blockIdx.x;
    int tid = threadIdx.x, lane = tid & 31, wid = tid >> 5;

    extern __shared__ char smem[];
    unsigned long long* keys = (unsigned long long*)(smem + 0);        // 32KB, by m
    float*          sx1   = (float*)(smem + 32768);
    float*          sy1   = (float*)(smem + 49152);
    float*          sx2   = (float*)(smem + 65536);
    float*          sy2   = (float*)(smem + 81920);
    float*          sar   = (float*)(smem + 98304);                    // ends 114688
    unsigned short* lists16 = (unsigned short*)(smem + 114688);        // 32 warps * 512 = 32KB
    int*            picks = (int*)(smem + 147456);                     // 4KB
    unsigned short* A     = (unsigned short*)(smem + 151552);          // 8KB
    unsigned short* wrow  = (unsigned short*)(smem + 159744);          // 8KB
    unsigned char*  scb   = (unsigned char*)(smem + 167936);           // class by m, 4KB
    unsigned char*  kem   = (unsigned char*)(smem + 172032);           // kept by m, 4KB
    __shared__ int wsum[32];
    __shared__ int hist[256];
    __shared__ int s_total, s_kept, s_target;
    __shared__ unsigned long long s_pre;
    __shared__ float s_out[NCL];

    const unsigned char* fl = g_flags + (size_t)b * NN;

    // ---- phase 1: dual order-preserving compaction (one packed block scan) ----
    int start = tid * RPT;
    int myA = 0, myW = 0;
    #pragma unroll
    for (int k = 0; k < RPT; k++) {
        int r = start + k;
        unsigned char f = (r < NN) ? fl[r] : 0;
        myA += f & 1; myW += f >> 1;
    }
    int pk = myA | (myW << 16);
    int s = pk;
    for (int o = 1; o < 32; o <<= 1) {
        int v = __shfl_up_sync(FULLM, s, o);
        if (lane >= o) s += v;
    }
    if (lane == 31) wsum[wid] = s;
    __syncthreads();
    if (wid == 0) {
        int w = wsum[lane];
        for (int o = 1; o < 32; o <<= 1) {
            int v = __shfl_up_sync(FULLM, w, o);
            if (lane >= o) w += v;
        }
        wsum[lane] = w;
        if (lane == 31) s_total = w;
    }
    __syncthreads();
    int excl = (wid ? wsum[wid - 1] : 0) + s - pk;
    int pa = excl & 0xffff;
    int pw = excl >> 16;
    #pragma unroll
    for (int k = 0; k < RPT; k++) {
        int r = start + k;
        unsigned char f = (r < NN) ? fl[r] : 0;
        if (f & 1) { if (pa < KNMS) A[pa] = (unsigned short)r; pa++; }
        if (f & 2) { if (pw < KNMS) wrow[pw] = (unsigned short)r; pw++; }
    }
    int C = s_total >> 16; if (C > KNMS) C = KNMS;
    if (tid < NCL) s_out[tid] = 0.0f;
    if (tid == 0) s_kept = 0;
    for (int t = tid; t < KNMS; t += 1024) kem[t] = 0;
    __syncthreads();

    // ---- phase 2: keys/boxes/areas/class by w-rank m ----
    for (int m = tid; m < C; m += 1024) {
        int r = wrow[m];
        keys[m] = ((unsigned long long)__float_as_uint(g_conf[b * NN + r]) << 32)
                | (unsigned long long)(~(unsigned)m);
        float4 bx = g_cbox[b * NN + r];
        sx1[m] = bx.x; sy1[m] = bx.y; sx2[m] = bx.z; sy2[m] = bx.w;
        sar[m] = __fmul_rn(__fsub_rn(bx.z, bx.x), __fsub_rn(bx.w, bx.y));
        scb[m] = g_j[b * NN + r];
    }
    __syncthreads();

    // ---- phase 3: per-class gather + warp rank-sort + warp greedy ----
    // Classes never overlap (offset 7680 >> box extent): cross-class IoU == 0.
    for (int c = wid; c < NCL; c += 32) {
        unsigned short* dst = lists16 + wid * 512;
        unsigned short* tmp = dst + 256;
        int n = 0;
        for (int base = 0; base < C; base += 32) {
            int t = base + lane;
            bool mm = (t < C) && (scb[t] == (unsigned char)c);
            unsigned bal = __ballot_sync(FULLM, mm);
            if (mm) {
                int pos = n + __popc(bal & ((1u << lane) - 1u));
                if (pos < CLCAP) tmp[pos] = (unsigned short)t;
            }
            n += __popc(bal);
        }
        if (n > CLCAP) n = CLCAP;
        __syncwarp();
        // rank-sort descending by key (keys unique -> perfect permutation)
        for (int e = lane; e < n; e += 32) {
            unsigned long long ke = keys[tmp[e]];
            int r = 0;
            for (int f = 0; f < n; f++) r += (keys[tmp[f]] > ke) ? 1 : 0;
            dst[r] = tmp[e];
        }
        __syncwarp();

        int kcnt = 0;
        unsigned rm = 0;   // removed: entry e owned by lane e&31, bit e>>5
        for (int i = 0; i < n; i++) {
            unsigned rmi = __shfl_sync(FULLM, rm, i & 31);
            if ((rmi >> (i >> 5)) & 1u) continue;   // uniform
            int mi = dst[i];
            kcnt++;
            if (lane == 0) kem[mi] = 1;
            float bx1 = sx1[mi], by1 = sy1[mi], bx2 = sx2[mi], by2 = sy2[mi];
            float ba = sar[mi];
            for (int k = 0, e = lane; e < n; k++, e += 32) {
                if (e > i && !((rm >> k) & 1u)) {
                    int mj = dst[e];
                    float iw = __fsub_rn(fminf(sx2[mj], bx2), fmaxf(sx1[mj], bx1));
                    float ih = __fsub_rn(fminf(sy2[mj], by2), fmaxf(sy1[mj], by1));
                    float inter = __fmul_rn(fmaxf(iw, 0.0f), fmaxf(ih, 0.0f));
                    float denom = __fsub_rn(__fadd_rn(sar[mj], ba), inter);
                    if (__fdiv_rn(inter, denom) > IOU_T) rm |= (1u << k);
                }
            }
            __syncwarp();
        }
        if (lane == 0 && kcnt) atomicAdd(&s_kept, kcnt);
    }
    __syncthreads();

    // ---- phase 4: radix select the MAXDET-th largest key among kept ----
    int keptTotal = s_kept;
    unsigned long long KT = 0ull;
    if (keptTotal > MAXDET) {
        if (tid == 0) { s_pre = 0ull; s_target = MAXDET; }
        __syncthreads();
        for (int shift = 56; shift >= 0; shift -= 8) {
            if (tid < 256) hist[tid] = 0;
            __syncthreads();
            unsigned long long pre = s_pre;
            for (int m = tid; m < C; m += 1024) {
                if (kem[m]) {
                    unsigned long long k = keys[m];
                    bool ok = (shift == 56) ||
                              ((k >> (shift + 8)) == (pre >> (shift + 8)));
                    if (ok) atomicAdd(&hist[(int)((k >> shift) & 0xFF)], 1);
                }
            }
            __syncthreads();
            if (wid == 0) {
                int s8 = 0;
                #pragma unroll
                for (int q = 0; q < 8; q++) s8 += hist[lane * 8 + q];
                int suf = s8;
                #pragma unroll
                for (int o = 1; o < 32; o <<= 1) {
                    int v = __shfl_down_sync(FULLM, suf, o);
                    if (lane + o < 32) suf += v;
                }
                int sufnext = suf - s8;
                int target = s_target;
                if (suf >= target && sufnext < target) {
                    int cacc = sufnext;
                    for (int q = 7; q >= 0; q--) {
                        int h = hist[lane * 8 + q];
                        cacc += h;
                        if (cacc >= target) {
                            s_pre = pre | ((unsigned long long)(lane * 8 + q) << shift);
                            s_target = target - (cacc - h);
                            break;
                        }
                    }
                }
            }
            __syncthreads();
        }
        KT = s_pre;   // exact 1000th-largest kept key (keys unique)
    }

    // ---- phase 5: prefix-scan over pick flags (m-ascending picks) ----
    int t0 = tid * 4;
    int k0 = (kem[t0]     && keys[t0]     >= KT) ? 1 : 0;
    int k1 = (kem[t0 + 1] && keys[t0 + 1] >= KT) ? 1 : 0;
    int k2 = (kem[t0 + 2] && keys[t0 + 2] >= KT) ? 1 : 0;
    int k3 = (kem[t0 + 3] && keys[t0 + 3] >= KT) ? 1 : 0;
    int sum4 = k0 + k1 + k2 + k3;
    int sc = sum4;
    for (int o = 1; o < 32; o <<= 1) {
        int v = __shfl_up_sync(FULLM, sc, o);
        if (lane >= o) sc += v;
    }
    if (lane == 31) wsum[wid] = sc;
    __syncthreads();
    if (wid == 0) {
        int w = wsum[lane];
        for (int o = 1; o < 32; o <<= 1) {
            int v = __shfl_up_sync(FULLM, w, o);
            if (lane >= o) w += v;
        }
        wsum[lane] = w;
        if (lane == 31) s_total = w;
    }
    __syncthreads();
    int base2 = (wid ? wsum[wid - 1] : 0) + (sc - sum4);
    int p0 = base2 + k0, p1 = p0 + k1, p2 = p1 + k2, p3 = p2 + k3;
    if (k0 && p0 <= MAXDET) picks[p0 - 1] = t0;
    if (k1 && p1 <= MAXDET) picks[p1 - 1] = t0 + 1;
    if (k2 && p2 <= MAXDET) picks[p2 - 1] = t0 + 2;
    if (k3 && p3 <= MAXDET) picks[p3 - 1] = t0 + 3;
    __syncthreads();

    // ---- phase 6: accumulation (warp per pick; reference's A[m] pick quirk) ----
    int cnt = s_total; if (cnt > MAXDET) cnt = MAXDET;
    float a0 = 0.0f, a1 = 0.0f, a2 = 0.0f;
    for (int t = wid; t < cnt; t += 32) {
        int m = picks[t];
        const float* pr = p + ((size_t)b * NN + A[m]) * NCH;
        float obj = pr[4];
        a0 += obj * pr[5 + lane];
        a1 += obj * pr[37 + lane];
        if (lane < 16) a2 += obj * pr[69 + lane];
    }
    atomicAdd(&s_out[lane], a0);
    atomicAdd(&s_out[32 + lane], a1);
    if (lane < 16) atomicAdd(&s_out[64 + lane], a2);
    __syncthreads();
    if (tid < NCL) out[b * NCL + tid] = s_out[tid];
}

// ---------------- launcher ----------------
extern "C" void kernel_launch(void* const* d_in, const int* in_sizes, int n_in,
                              void* d_out, int out_size) {
    const float* p = (const float*)d_in[0];
    float* out = (float*)d_out;

    k_all<<<dim3((NN + RPB - 1) / RPB, BB), RPB>>>(p);
    int smem = 176128;
    cudaFuncSetAttribute(k_fused, cudaFuncAttributeMaxDynamicSharedMemorySize, smem);
    k_fused<<<BB, 1024, smem>>>(p, out);
}

// round 7
// speedup vs baseline: 11.0100x; 1.0249x over previous
#include <cuda_runtime.h>
#include <cstdint>

#define BB   32
#define NN   25200
#define NCH  85
#define NCL  80
#define KNMS 4096
#define CONF_T 0.25f
#define IOU_T  0.45f
#define MAXDET 1000
#define MAXWH  7680.0f
#define CLCAP 256
#define FULLM 0xffffffffu
#define RPB  256           // rows per k_all block (= 8 mask words)
#define NWORDS 788         // ceil(25200/32)

__device__ unsigned g_maskA[BB * NWORDS];    // xc bitmask
__device__ unsigned g_maskW[BB * NWORDS];    // w bitmask
__device__ float         g_conf[BB * NN];    // by row (w rows)
__device__ unsigned char g_j[BB * NN];       // by row (w rows)
__device__ float4        g_cbox[BB * NN];    // by row (w rows)

// ---------------- K1: full-grid row scan + candidate scoring -> bitmasks ----------------
__global__ void k_all(const float* __restrict__ p) {
    int b = blockIdx.y;
    int r0 = blockIdx.x * RPB;
    int tid = threadIdx.x, lane = tid & 31, wid = tid >> 5;
    __shared__ unsigned short wl[RPB];
    __shared__ unsigned sm_wmask[RPB / 32];
    __shared__ int s_cnt;
    if (tid == 0) s_cnt = 0;
    if (tid < RPB / 32) sm_wmask[tid] = 0u;
    __syncthreads();

    int row = r0 + tid;
    bool xc = false;
    if (row < NN) {
        float obj = p[((size_t)b * NN + row) * NCH + 4];
        xc = obj > CONF_T;
    }
    unsigned bal = __ballot_sync(FULLM, xc);
    if (lane == 0 && row < NN)
        g_maskA[b * NWORDS + (row >> 5)] = bal;
    int base = 0;
    if (lane == 0 && bal) base = atomicAdd(&s_cnt, __popc(bal));
    base = __shfl_sync(FULLM, base, 0);
    if (xc) wl[base + __popc(bal & ((1u << lane) - 1u))] = (unsigned short)row;
    __syncthreads();

    int cnt = s_cnt;
    for (int k = wid; k < cnt; k += 8) {
        int r = wl[k];
        const float* pr = p + ((size_t)b * NN + r) * NCH;
        float v0 = pr[lane];
        float v1 = pr[lane + 32];
        float v2 = (lane < 21) ? pr[lane + 64] : 0.0f;
        float obj = __shfl_sync(FULLM, v0, 4);

        float bv = -3.4e38f; int bi = 1 << 20;
        if (lane >= 5) { bv = obj * v0; bi = lane - 5; }          // cls 0..26
        { float sc = obj * v1; int i1 = lane + 27;                // cls 27..58
          if (sc > bv) { bv = sc; bi = i1; } }
        if (lane < 21) { float sc = obj * v2; int i2 = lane + 59; // cls 59..79
          if (sc > bv) { bv = sc; bi = i2; } }
        for (int off = 16; off; off >>= 1) {
            float ov = __shfl_xor_sync(FULLM, bv, off);
            int   oi = __shfl_xor_sync(FULLM, bi, off);
            if (ov > bv || (ov == bv && oi < bi)) { bv = ov; bi = oi; }
        }
        float x  = __shfl_sync(FULLM, v0, 0);
        float y  = __shfl_sync(FULLM, v0, 1);
        float ww = __shfl_sync(FULLM, v0, 2);
        float hh = __shfl_sync(FULLM, v0, 3);
        if (lane == 0 && bv > CONF_T) {
            atomicOr(&sm_wmask[(r - r0) >> 5], 1u << (r & 31));
            g_conf[b * NN + r] = bv;
            g_j[b * NN + r] = (unsigned char)bi;
            float off = (float)bi * MAXWH;
            float hw = __fmul_rn(ww, 0.5f);
            float hv = __fmul_rn(hh, 0.5f);
            float4 bx;
            bx.x = __fadd_rn(__fsub_rn(x, hw), off);
            bx.y = __fadd_rn(__fsub_rn(y, hv), off);
            bx.z = __fadd_rn(__fadd_rn(x, hw), off);
            bx.w = __fadd_rn(__fadd_rn(y, hv), off);
            g_cbox[b * NN + r] = bx;
        }
    }
    __syncthreads();
    if (tid < RPB / 32) {
        int word = (r0 >> 5) + tid;
        if (word < NWORDS && word * 32 < NN)
            g_maskW[b * NWORDS + word] = sm_wmask[tid];
    }
}

// ---------------- K2: per-image serial core (bitmask scan, no global sort) ----------------
__global__ void k_fused(const float* __restrict__ p, float* __restrict__ out) {
    int b = blockIdx.x;
    int tid = threadIdx.x, lane = tid & 31, wid = tid >> 5;

    extern __shared__ char smem[];
    unsigned long long* keys = (unsigned long long*)(smem + 0);        // 32KB, by m
    float*          sx1   = (float*)(smem + 32768);
    float*          sy1   = (float*)(smem + 49152);
    float*          sx2   = (float*)(smem + 65536);
    float*          sy2   = (float*)(smem + 81920);
    float*          sar   = (float*)(smem + 98304);                    // ends 114688
    unsigned short* lists16 = (unsigned short*)(smem + 114688);        // 32 warps * 512 = 32KB
    int*            picks = (int*)(smem + 147456);                     // 4KB
    unsigned short* A     = (unsigned short*)(smem + 151552);          // 8KB
    unsigned short* wrow  = (unsigned short*)(smem + 159744);          // 8KB
    unsigned char*  scb   = (unsigned char*)(smem + 167936);           // class by m, 4KB
    unsigned char*  kem   = (unsigned char*)(smem + 172032);           // kept by m, 4KB
    __shared__ int wsum[32];
    __shared__ int hist[256];
    __shared__ int s_total, s_kept, s_target;
    __shared__ unsigned long long s_pre;
    __shared__ float s_out[NCL];

    // ---- phase 1: dual bitmask compaction (one packed block scan) ----
    unsigned wa = 0, wb = 0;
    if (tid < NWORDS) {
        wa = g_maskA[b * NWORDS + tid];
        wb = g_maskW[b * NWORDS + tid];
    }
    int pk = __popc(wa) | (__popc(wb) << 16);
    int s = pk;
    for (int o = 1; o < 32; o <<= 1) {
        int v = __shfl_up_sync(FULLM, s, o);
        if (lane >= o) s += v;
    }
    if (lane == 31) wsum[wid] = s;
    __syncthreads();
    if (wid == 0) {
        int w = wsum[lane];
        for (int o = 1; o < 32; o <<= 1) {
            int v = __shfl_up_sync(FULLM, w, o);
            if (lane >= o) w += v;
        }
        wsum[lane] = w;
        if (lane == 31) s_total = w;
    }
    __syncthreads();
    int excl = (wid ? wsum[wid - 1] : 0) + s - pk;
    {
        int pa = excl & 0xffff;
        unsigned w = wa;
        while (w) {
            int bit = __ffs(w) - 1; w &= w - 1;
            if (pa < KNMS) A[pa] = (unsigned short)(tid * 32 + bit);
            pa++;
        }
        int pw = excl >> 16;
        w = wb;
        while (w) {
            int bit = __ffs(w) - 1; w &= w - 1;
            if (pw < KNMS) wrow[pw] = (unsigned short)(tid * 32 + bit);
            pw++;
        }
    }
    int C = s_total >> 16; if (C > KNMS) C = KNMS;
    if (tid < NCL) s_out[tid] = 0.0f;
    if (tid == 0) s_kept = 0;
    for (int t = tid; t < KNMS; t += 1024) kem[t] = 0;
    __syncthreads();

    // ---- phase 2: keys/boxes/areas/class by w-rank m ----
    for (int m = tid; m < C; m += 1024) {
        int r = wrow[m];
        keys[m] = ((unsigned long long)__float_as_uint(g_conf[b * NN + r]) << 32)
                | (unsigned long long)(~(unsigned)m);
        float4 bx = g_cbox[b * NN + r];
        sx1[m] = bx.x; sy1[m] = bx.y; sx2[m] = bx.z; sy2[m] = bx.w;
        sar[m] = __fmul_rn(__fsub_rn(bx.z, bx.x), __fsub_rn(bx.w, bx.y));
        scb[m] = g_j[b * NN + r];
    }
    __syncthreads();

    // ---- phase 3: per-class gather + warp rank-sort + warp greedy ----
    // Classes never overlap (offset 7680 >> box extent): cross-class IoU == 0.
    for (int c = wid; c < NCL; c += 32) {
        unsigned short* dst = lists16 + wid * 512;
        unsigned short* tmp = dst + 256;
        int n = 0;
        for (int base = 0; base < C; base += 32) {
            int t = base + lane;
            bool mm = (t < C) && (scb[t] == (unsigned char)c);
            unsigned bal = __ballot_sync(FULLM, mm);
            if (mm) {
                int pos = n + __popc(bal & ((1u << lane) - 1u));
                if (pos < CLCAP) tmp[pos] = (unsigned short)t;
            }
            n += __popc(bal);
        }
        if (n > CLCAP) n = CLCAP;
        __syncwarp();
        // rank-sort descending by key (keys unique -> perfect permutation)
        for (int e = lane; e < n; e += 32) {
            unsigned long long ke = keys[tmp[e]];
            int r = 0;
            for (int f = 0; f < n; f++) r += (keys[tmp[f]] > ke) ? 1 : 0;
            dst[r] = tmp[e];
        }
        __syncwarp();

        int kcnt = 0;
        unsigned rm = 0;   // removed: entry e owned by lane e&31, bit e>>5
        for (int i = 0; i < n; i++) {
            unsigned rmi = __shfl_sync(FULLM, rm, i & 31);
            if ((rmi >> (i >> 5)) & 1u) continue;   // uniform
            int mi = dst[i];
            kcnt++;
            if (lane == 0) kem[mi] = 1;
            float bx1 = sx1[mi], by1 = sy1[mi], bx2 = sx2[mi], by2 = sy2[mi];
            float ba = sar[mi];
            for (int k = 0, e = lane; e < n; k++, e += 32) {
                if (e > i && !((rm >> k) & 1u)) {
                    int mj = dst[e];
                    float iw = __fsub_rn(fminf(sx2[mj], bx2), fmaxf(sx1[mj], bx1));
                    float ih = __fsub_rn(fminf(sy2[mj], by2), fmaxf(sy1[mj], by1));
                    float inter = __fmul_rn(fmaxf(iw, 0.0f), fmaxf(ih, 0.0f));
                    float denom = __fsub_rn(__fadd_rn(sar[mj], ba), inter);
                    if (__fdiv_rn(inter, denom) > IOU_T) rm |= (1u << k);
                }
            }
            __syncwarp();
        }
        if (lane == 0 && kcnt) atomicAdd(&s_kept, kcnt);
    }
    __syncthreads();

    // ---- phase 4: radix select the MAXDET-th largest key among kept ----
    int keptTotal = s_kept;
    unsigned long long KT = 0ull;
    if (keptTotal > MAXDET) {
        if (tid == 0) { s_pre = 0ull; s_target = MAXDET; }
        __syncthreads();
        for (int shift = 56; shift >= 0; shift -= 8) {
            if (tid < 256) hist[tid] = 0;
            __syncthreads();
            unsigned long long pre = s_pre;
            for (int m = tid; m < C; m += 1024) {
                if (kem[m]) {
                    unsigned long long k = keys[m];
                    bool ok = (shift == 56) ||
                              ((k >> (shift + 8)) == (pre >> (shift + 8)));
                    if (ok) atomicAdd(&hist[(int)((k >> shift) & 0xFF)], 1);
                }
            }
            __syncthreads();
            if (wid == 0) {
                int s8 = 0;
                #pragma unroll
                for (int q = 0; q < 8; q++) s8 += hist[lane * 8 + q];
                int suf = s8;
                #pragma unroll
                for (int o = 1; o < 32; o <<= 1) {
                    int v = __shfl_down_sync(FULLM, suf, o);
                    if (lane + o < 32) suf += v;
                }
                int sufnext = suf - s8;
                int target = s_target;
                if (suf >= target && sufnext < target) {
                    int cacc = sufnext;
                    for (int q = 7; q >= 0; q--) {
                        int h = hist[lane * 8 + q];
                        cacc += h;
                        if (cacc >= target) {
                            s_pre = pre | ((unsigned long long)(lane * 8 + q) << shift);
                            s_target = target - (cacc - h);
                            break;
                        }
                    }
                }
            }
            __syncthreads();
        }
        KT = s_pre;   // exact 1000th-largest kept key (keys unique)
    }

    // ---- phase 5: prefix-scan over pick flags (m-ascending picks) ----
    int t0 = tid * 4;
    int k0 = (kem[t0]     && keys[t0]     >= KT) ? 1 : 0;
    int k1 = (kem[t0 + 1] && keys[t0 + 1] >= KT) ? 1 : 0;
    int k2 = (kem[t0 + 2] && keys[t0 + 2] >= KT) ? 1 : 0;
    int k3 = (kem[t0 + 3] && keys[t0 + 3] >= KT) ? 1 : 0;
    int sum4 = k0 + k1 + k2 + k3;
    int sc = sum4;
    for (int o = 1; o < 32; o <<= 1) {
        int v = __shfl_up_sync(FULLM, sc, o);
        if (lane >= o) sc += v;
    }
    if (lane == 31) wsum[wid] = sc;
    __syncthreads();
    if (wid == 0) {
        int w = wsum[lane];
        for (int o = 1; o < 32; o <<= 1) {
            int v = __shfl_up_sync(FULLM, w, o);
            if (lane >= o) w += v;
        }
        wsum[lane] = w;
        if (lane == 31) s_total = w;
    }
    __syncthreads();
    int base2 = (wid ? wsum[wid - 1] : 0) + (sc - sum4);
    int p0 = base2 + k0, p1 = p0 + k1, p2 = p1 + k2, p3 = p2 + k3;
    if (k0 && p0 <= MAXDET) picks[p0 - 1] = t0;
    if (k1 && p1 <= MAXDET) picks[p1 - 1] = t0 + 1;
    if (k2 && p2 <= MAXDET) picks[p2 - 1] = t0 + 2;
    if (k3 && p3 <= MAXDET) picks[p3 - 1] = t0 + 3;
    __syncthreads();

    // ---- phase 6: accumulation (warp per pick; reference's A[m] pick quirk) ----
    int cnt = s_total; if (cnt > MAXDET) cnt = MAXDET;
    float a0 = 0.0f, a1 = 0.0f, a2 = 0.0f;
    for (int t = wid; t < cnt; t += 32) {
        int m = picks[t];
        const float* pr = p + ((size_t)b * NN + A[m]) * NCH;
        float obj = pr[4];
        a0 += obj * pr[5 + lane];
        a1 += obj * pr[37 + lane];
        if (lane < 16) a2 += obj * pr[69 + lane];
    }
    atomicAdd(&s_out[lane], a0);
    atomicAdd(&s_out[32 + lane], a1);
    if (lane < 16) atomicAdd(&s_out[64 + lane], a2);
    __syncthreads();
    if (tid < NCL) out[b * NCL + tid] = s_out[tid];
}

// ---------------- launcher ----------------
extern "C" void kernel_launch(void* const* d_in, const int* in_sizes, int n_in,
                              void* d_out, int out_size) {
    const float* p = (const float*)d_in[0];
    float* out = (float*)d_out;

    k_all<<<dim3((NN + RPB - 1) / RPB, BB), RPB>>>(p);
    int smem = 176128;
    cudaFuncSetAttribute(k_fused, cudaFuncAttributeMaxDynamicSharedMemorySize, smem);
    k_fused<<<BB, 1024, smem>>>(p, out);
}

// round 8
// speedup vs baseline: 12.7598x; 1.1589x over previous
#include <cuda_runtime.h>
#include <cstdint>

#define BB   32
#define NN   25200
#define NCH  85
#define NCL  80
#define KNMS 4096
#define CONF_T 0.25f
#define IOU_T  0.45f
#define MAXDET 1000
#define MAXWH  7680.0f
#define CLCAP 256
#define FULLM 0xffffffffu
#define RPB  256           // rows per k_all block (= 8 mask words)
#define NWORDS 788         // ceil(25200/32)

__device__ unsigned g_maskA[BB * NWORDS];    // xc bitmask
__device__ unsigned g_maskW[BB * NWORDS];    // w bitmask
__device__ float         g_conf[BB * NN];    // by row (w rows)
__device__ unsigned char g_j[BB * NN];       // by row (w rows)
__device__ float4        g_cbox[BB * NN];    // by row (w rows)

__device__ unsigned short g_A16[BB * KNMS];       // xc rank -> row
__device__ unsigned long long g_keys[BB * KNMS];  // by w-rank m
__device__ float4        g_box[BB * KNMS];        // by w-rank m
__device__ unsigned short g_cls[BB * NCL * CLCAP];// per-class m lists
__device__ int           g_clsn[BB * NCL];
__device__ unsigned char g_kem[BB * KNMS];        // kept flag by m
__device__ int           g_kept[BB];
__device__ int           g_cw[BB];                // C per image

// ---------------- K1: full-grid row scan + candidate scoring -> bitmasks ----------------
__global__ void k_all(const float* __restrict__ p) {
    int b = blockIdx.y;
    int r0 = blockIdx.x * RPB;
    int tid = threadIdx.x, lane = tid & 31, wid = tid >> 5;
    __shared__ unsigned short wl[RPB];
    __shared__ unsigned sm_wmask[RPB / 32];
    __shared__ int s_cnt;
    if (tid == 0) s_cnt = 0;
    if (tid < RPB / 32) sm_wmask[tid] = 0u;
    __syncthreads();

    int row = r0 + tid;
    bool xc = false;
    if (row < NN) {
        float obj = p[((size_t)b * NN + row) * NCH + 4];
        xc = obj > CONF_T;
    }
    unsigned bal = __ballot_sync(FULLM, xc);
    if (lane == 0 && row < NN)
        g_maskA[b * NWORDS + (row >> 5)] = bal;
    int base = 0;
    if (lane == 0 && bal) base = atomicAdd(&s_cnt, __popc(bal));
    base = __shfl_sync(FULLM, base, 0);
    if (xc) wl[base + __popc(bal & ((1u << lane) - 1u))] = (unsigned short)row;
    __syncthreads();

    int cnt = s_cnt;
    for (int k = wid; k < cnt; k += 8) {
        int r = wl[k];
        const float* pr = p + ((size_t)b * NN + r) * NCH;
        float v0 = pr[lane];
        float v1 = pr[lane + 32];
        float v2 = (lane < 21) ? pr[lane + 64] : 0.0f;
        float obj = __shfl_sync(FULLM, v0, 4);

        float bv = -3.4e38f; int bi = 1 << 20;
        if (lane >= 5) { bv = obj * v0; bi = lane - 5; }          // cls 0..26
        { float sc = obj * v1; int i1 = lane + 27;                // cls 27..58
          if (sc > bv) { bv = sc; bi = i1; } }
        if (lane < 21) { float sc = obj * v2; int i2 = lane + 59; // cls 59..79
          if (sc > bv) { bv = sc; bi = i2; } }
        for (int off = 16; off; off >>= 1) {
            float ov = __shfl_xor_sync(FULLM, bv, off);
            int   oi = __shfl_xor_sync(FULLM, bi, off);
            if (ov > bv || (ov == bv && oi < bi)) { bv = ov; bi = oi; }
        }
        float x  = __shfl_sync(FULLM, v0, 0);
        float y  = __shfl_sync(FULLM, v0, 1);
        float ww = __shfl_sync(FULLM, v0, 2);
        float hh = __shfl_sync(FULLM, v0, 3);
        if (lane == 0 && bv > CONF_T) {
            atomicOr(&sm_wmask[(r - r0) >> 5], 1u << (r & 31));
            g_conf[b * NN + r] = bv;
            g_j[b * NN + r] = (unsigned char)bi;
            float off = (float)bi * MAXWH;
            float hw = __fmul_rn(ww, 0.5f);
            float hv = __fmul_rn(hh, 0.5f);
            float4 bx;
            bx.x = __fadd_rn(__fsub_rn(x, hw), off);
            bx.y = __fadd_rn(__fsub_rn(y, hv), off);
            bx.z = __fadd_rn(__fadd_rn(x, hw), off);
            bx.w = __fadd_rn(__fadd_rn(y, hv), off);
            g_cbox[b * NN + r] = bx;
        }
    }
    __syncthreads();
    if (tid < RPB / 32) {
        int word = (r0 >> 5) + tid;
        if (word < NWORDS && word * 32 < NN)
            g_maskW[b * NWORDS + word] = sm_wmask[tid];
    }
}

// ---------------- K2: per-image prep: scan + scatter + class bucketing ----------------
__global__ void k_prep() {
    int b = blockIdx.x;
    int tid = threadIdx.x, lane = tid & 31, wid = tid >> 5;
    __shared__ int wsum[32];
    __shared__ int s_total;
    __shared__ int clsCnt[NCL];

    unsigned wa = 0, wb = 0;
    if (tid < NWORDS) {
        wa = g_maskA[b * NWORDS + tid];
        wb = g_maskW[b * NWORDS + tid];
    }
    if (tid < NCL) clsCnt[tid] = 0;
    if (tid == 0) g_kept[b] = 0;
    { // zero kept flags (4096 B as 1024 ints)
        ((int*)(g_kem + (size_t)b * KNMS))[tid] = 0;
    }
    int pk = __popc(wa) | (__popc(wb) << 16);
    int s = pk;
    for (int o = 1; o < 32; o <<= 1) {
        int v = __shfl_up_sync(FULLM, s, o);
        if (lane >= o) s += v;
    }
    if (lane == 31) wsum[wid] = s;
    __syncthreads();
    if (wid == 0) {
        int w = wsum[lane];
        for (int o = 1; o < 32; o <<= 1) {
            int v = __shfl_up_sync(FULLM, w, o);
            if (lane >= o) w += v;
        }
        wsum[lane] = w;
        if (lane == 31) s_total = w;
    }
    __syncthreads();
    int excl = (wid ? wsum[wid - 1] : 0) + s - pk;
    {
        int pa = excl & 0xffff;
        unsigned w = wa;
        while (w) {
            int bit = __ffs(w) - 1; w &= w - 1;
            if (pa < KNMS) g_A16[b * KNMS + pa] = (unsigned short)(tid * 32 + bit);
            pa++;
        }
        int pw = excl >> 16;
        w = wb;
        while (w) {
            int bit = __ffs(w) - 1; w &= w - 1;
            int r = tid * 32 + bit;
            if (pw < KNMS) {
                g_keys[b * KNMS + pw] =
                    ((unsigned long long)__float_as_uint(g_conf[b * NN + r]) << 32)
                  | (unsigned long long)(~(unsigned)pw);
                g_box[b * KNMS + pw] = g_cbox[b * NN + r];
                int c = g_j[b * NN + r];
                int slot = atomicAdd(&clsCnt[c], 1);
                if (slot < CLCAP)
                    g_cls[((size_t)b * NCL + c) * CLCAP + slot] = (unsigned short)pw;
            }
            pw++;
        }
    }
    __syncthreads();
    if (tid == 0) {
        int C = s_total >> 16; if (C > KNMS) C = KNMS;
        g_cw[b] = C;
    }
    if (tid < NCL) {
        int n = clsCnt[tid]; if (n > CLCAP) n = CLCAP;
        g_clsn[b * NCL + tid] = n;
    }
}

// ---------------- K3: one warp per (image, class) greedy NMS ----------------
// Classes never overlap (offset 7680 >> box extent): cross-class IoU == 0.
__global__ void k_greedy() {
    int b = blockIdx.y;
    int tid = threadIdx.x, lane = tid & 31, wid = tid >> 5;
    int c = blockIdx.x * 8 + wid;

    extern __shared__ char smem[];
    char* wbase = smem + wid * 8192;
    unsigned long long* sk = (unsigned long long*)(wbase + 0);    // 256*8
    float4*         sbx = (float4*)(wbase + 2048);                // 256*16
    float*          sar = (float*)(wbase + 6144);                 // 256*4
    unsigned short* sml = (unsigned short*)(wbase + 7168);        // 256*2
    unsigned short* dst = (unsigned short*)(wbase + 7680);        // 256*2

    if (c >= NCL) return;
    int n = g_clsn[b * NCL + c];
    if (n == 0) return;

    for (int e = lane; e < n; e += 32) {
        int m = g_cls[((size_t)b * NCL + c) * CLCAP + e];
        sml[e] = (unsigned short)m;
        sk[e] = g_keys[b * KNMS + m];
        float4 bx = g_box[b * KNMS + m];
        sbx[e] = bx;
        sar[e] = __fmul_rn(__fsub_rn(bx.z, bx.x), __fsub_rn(bx.w, bx.y));
    }
    __syncwarp();
    // rank-sort descending by key (keys unique -> perfect permutation)
    for (int e = lane; e < n; e += 32) {
        unsigned long long ke = sk[e];
        int r = 0;
        for (int f = 0; f < n; f++) r += (sk[f] > ke) ? 1 : 0;
        dst[r] = (unsigned short)e;
    }
    __syncwarp();

    int kcnt = 0;
    unsigned rm = 0;   // removed: entry e owned by lane e&31, bit e>>5
    for (int i = 0; i < n; i++) {
        unsigned rmi = __shfl_sync(FULLM, rm, i & 31);
        if ((rmi >> (i >> 5)) & 1u) continue;   // uniform
        int mi = dst[i];
        kcnt++;
        if (lane == 0) g_kem[b * KNMS + sml[mi]] = 1;
        float4 bi4 = sbx[mi];
        float ba = sar[mi];
        for (int k = 0, e = lane; e < n; k++, e += 32) {
            if (e > i && !((rm >> k) & 1u)) {
                int mj = dst[e];
                float4 bj = sbx[mj];
                float iw = __fsub_rn(fminf(bj.z, bi4.z), fmaxf(bj.x, bi4.x));
                float ih = __fsub_rn(fminf(bj.w, bi4.w), fmaxf(bj.y, bi4.y));
                float inter = __fmul_rn(fmaxf(iw, 0.0f), fmaxf(ih, 0.0f));
                float denom = __fsub_rn(__fadd_rn(sar[mj], ba), inter);
                if (__fdiv_rn(inter, denom) > IOU_T) rm |= (1u << k);
            }
        }
        __syncwarp();
    }
    if (lane == 0 && kcnt) atomicAdd(&g_kept[b], kcnt);
}

// ---------------- K4: radix select + cap + accumulation ----------------
__global__ void k_final(const float* __restrict__ p, float* __restrict__ out) {
    int b = blockIdx.x;
    int tid = threadIdx.x, lane = tid & 31, wid = tid >> 5;

    extern __shared__ char smem[];
    unsigned long long* keys = (unsigned long long*)(smem + 0);    // 32KB
    int*            picks = (int*)(smem + 32768);                  // 4KB
    unsigned short* srow  = (unsigned short*)(smem + 36864);       // 2KB
    unsigned char*  kem   = (unsigned char*)(smem + 38912);        // 4KB
    __shared__ int wsum[32];
    __shared__ int hist[256];
    __shared__ int s_total, s_target;
    __shared__ unsigned long long s_pre;
    __shared__ float s_out[NCL];

    int C = g_cw[b];
    int keptTotal = g_kept[b];
    // stage keys + kem
    for (int t = tid; t < KNMS; t += 1024) {
        keys[t] = (t < C) ? g_keys[b * KNMS + t] : 0ull;
        kem[t] = g_kem[b * KNMS + t];
    }
    if (tid < NCL) s_out[tid] = 0.0f;
    __syncthreads();

    // radix select the MAXDET-th largest kept key (keys unique)
    unsigned long long KT = 0ull;
    if (keptTotal > MAXDET) {
        if (tid == 0) { s_pre = 0ull; s_target = MAXDET; }
        __syncthreads();
        for (int shift = 56; shift >= 0; shift -= 8) {
            if (tid < 256) hist[tid] = 0;
            __syncthreads();
            unsigned long long pre = s_pre;
            for (int m = tid; m < C; m += 1024) {
                if (kem[m]) {
                    unsigned long long k = keys[m];
                    bool ok = (shift == 56) ||
                              ((k >> (shift + 8)) == (pre >> (shift + 8)));
                    if (ok) atomicAdd(&hist[(int)((k >> shift) & 0xFF)], 1);
                }
            }
            __syncthreads();
            if (wid == 0) {
                int s8 = 0;
                #pragma unroll
                for (int q = 0; q < 8; q++) s8 += hist[lane * 8 + q];
                int suf = s8;
                #pragma unroll
                for (int o = 1; o < 32; o <<= 1) {
                    int v = __shfl_down_sync(FULLM, suf, o);
                    if (lane + o < 32) suf += v;
                }
                int sufnext = suf - s8;
                int target = s_target;
                if (suf >= target && sufnext < target) {
                    int cacc = sufnext;
                    for (int q = 7; q >= 0; q--) {
                        int h = hist[lane * 8 + q];
                        cacc += h;
                        if (cacc >= target) {
                            s_pre = pre | ((unsigned long long)(lane * 8 + q) << shift);
                            s_target = target - (cacc - h);
                            break;
                        }
                    }
                }
            }
            __syncthreads();
        }
        KT = s_pre;
    }

    // prefix over pick flags (m-ascending)
    int t0 = tid * 4;
    int k0 = (kem[t0]     && keys[t0]     >= KT) ? 1 : 0;
    int k1 = (kem[t0 + 1] && keys[t0 + 1] >= KT) ? 1 : 0;
    int k2 = (kem[t0 + 2] && keys[t0 + 2] >= KT) ? 1 : 0;
    int k3 = (kem[t0 + 3] && keys[t0 + 3] >= KT) ? 1 : 0;
    int sum4 = k0 + k1 + k2 + k3;
    int sc = sum4;
    for (int o = 1; o < 32; o <<= 1) {
        int v = __shfl_up_sync(FULLM, sc, o);
        if (lane >= o) sc += v;
    }
    if (lane == 31) wsum[wid] = sc;
    __syncthreads();
    if (wid == 0) {
        int w = wsum[lane];
        for (int o = 1; o < 32; o <<= 1) {
            int v = __shfl_up_sync(FULLM, w, o);
            if (lane >= o) w += v;
        }
        wsum[lane] = w;
        if (lane == 31) s_total = w;
    }
    __syncthreads();
    int base2 = (wid ? wsum[wid - 1] : 0) + (sc - sum4);
    int p0 = base2 + k0, p1 = p0 + k1, p2 = p1 + k2, p3 = p2 + k3;
    if (k0 && p0 <= MAXDET) picks[p0 - 1] = t0;
    if (k1 && p1 <= MAXDET) picks[p1 - 1] = t0 + 1;
    if (k2 && p2 <= MAXDET) picks[p2 - 1] = t0 + 2;
    if (k3 && p3 <= MAXDET) picks[p3 - 1] = t0 + 3;
    __syncthreads();

    int cnt = s_total; if (cnt > MAXDET) cnt = MAXDET;
    // stage row indices (reference's A[m] pick quirk), full MLP
    for (int t = tid; t < cnt; t += 1024)
        srow[t] = g_A16[b * KNMS + picks[t]];
    __syncthreads();

    // accumulation: warp per pick, 2-stage pipeline
    float a0 = 0.0f, a1 = 0.0f, a2 = 0.0f;
    int t = wid;
    float obj = 0.0f, c0 = 0.0f, c1 = 0.0f, c2 = 0.0f;
    if (t < cnt) {
        const float* pr = p + ((size_t)b * NN + srow[t]) * NCH;
        obj = pr[4];
        c0 = pr[5 + lane];
        c1 = pr[37 + lane];
        c2 = (lane < 16) ? pr[69 + lane] : 0.0f;
    }
    while (t < cnt) {
        int t2 = t + 32;
        float obj2 = 0.0f, d0 = 0.0f, d1 = 0.0f, d2 = 0.0f;
        if (t2 < cnt) {
            const float* pr2 = p + ((size_t)b * NN + srow[t2]) * NCH;
            obj2 = pr2[4];
            d0 = pr2[5 + lane];
            d1 = pr2[37 + lane];
            d2 = (lane < 16) ? pr2[69 + lane] : 0.0f;
        }
        a0 += obj * c0;
        a1 += obj * c1;
        a2 += obj * c2;
        obj = obj2; c0 = d0; c1 = d1; c2 = d2;
        t = t2;
    }
    atomicAdd(&s_out[lane], a0);
    atomicAdd(&s_out[32 + lane], a1);
    if (lane < 16) atomicAdd(&s_out[64 + lane], a2);
    __syncthreads();
    if (tid < NCL) out[b * NCL + tid] = s_out[tid];
}

// ---------------- launcher ----------------
extern "C" void kernel_launch(void* const* d_in, const int* in_sizes, int n_in,
                              void* d_out, int out_size) {
    const float* p = (const float*)d_in[0];
    float* out = (float*)d_out;

    k_all<<<dim3((NN + RPB - 1) / RPB, BB), RPB>>>(p);
    k_prep<<<BB, 1024>>>();
    cudaFuncSetAttribute(k_greedy, cudaFuncAttributeMaxDynamicSharedMemorySize, 65536);
    k_greedy<<<dim3(10, BB), 256, 65536>>>();
    cudaFuncSetAttribute(k_final, cudaFuncAttributeMaxDynamicSharedMemorySize, 43008);
    k_final<<<BB, 1024, 43008>>>(p, out);
}